// round 1
// baseline (speedup 1.0000x reference)
#include <cuda_runtime.h>

// Problem constants (fixed by setup_inputs)
#define BS_TOT 2048      // B*S
#define E_DIM  768
#define E4     192       // E/4
#define K_NB   36
#define H_NUM  4

// ---------------- scratch (device globals; no allocations) ----------------
__device__ float g_u[H_NUM * E_DIM];                    // gamma ⊙ (W1 @ W2y)
__device__ float g_ydot[BS_TOT * K_NB * H_NUM];         // yhat·u per (n,k,h)
__device__ float g_mu[BS_TOT * K_NB];
__device__ float g_rstd[BS_TOT * K_NB];
__device__ float g_gbuf[(long)H_NUM * BS_TOT * E_DIM];  // GEMM-D input per head
__device__ float g_cat[(long)BS_TOT * H_NUM * E_DIM];   // concat of head outputs

__device__ __forceinline__ float gelu_tanh(float v) {
    const float c = 0.7978845608028654f;   // sqrt(2/pi)
    float t = tanhf(c * (v + 0.044715f * v * v * v));
    return 0.5f * v * (1.0f + t);
}

// ---------------- kernel P: u[h][i] = gamma[h][i] * sum_j W1[h][i][j]*W2y[h][j]
__global__ void prep_u(const float* __restrict__ W1,
                       const float* __restrict__ W2y,
                       const float* __restrict__ gamma) {
    int warp = (blockIdx.x * blockDim.x + threadIdx.x) >> 5;
    int lane = threadIdx.x & 31;
    if (warp >= H_NUM * E_DIM) return;
    int h = warp / E_DIM;
    const float* wrow = W1 + (long)warp * E_DIM;       // warp = h*E + i
    const float* w2 = W2y + h * E_DIM;
    float s = 0.f;
    #pragma unroll 4
    for (int j = lane; j < E_DIM; j += 32) s += wrow[j] * w2[j];
    #pragma unroll
    for (int o = 16; o; o >>= 1) s += __shfl_xor_sync(0xffffffffu, s, o);
    if (lane == 0) g_u[warp] = gamma[warp] * s;
}

// ---------------- kernel A: per (n,k) row of y: mean, rstd, 4 dots with u[h]
__global__ __launch_bounds__(256) void ypass1(const float* __restrict__ y) {
    __shared__ float4 u_s[H_NUM * E4];
    const float4* u4 = (const float4*)g_u;
    for (int i = threadIdx.x; i < H_NUM * E4; i += blockDim.x) u_s[i] = u4[i];
    __syncthreads();

    int warp = threadIdx.x >> 5, lane = threadIdx.x & 31;
    int row = blockIdx.x * 8 + warp;                   // 0..73727
    const float4* yr = (const float4*)y + (long)row * E4;

    float4 v[6];
    float s = 0.f, sq = 0.f;
    #pragma unroll
    for (int j = 0; j < 6; j++) {
        v[j] = yr[lane + 32 * j];
        s  += v[j].x + v[j].y + v[j].z + v[j].w;
        sq += v[j].x * v[j].x + v[j].y * v[j].y + v[j].z * v[j].z + v[j].w * v[j].w;
    }
    #pragma unroll
    for (int o = 16; o; o >>= 1) {
        s  += __shfl_xor_sync(0xffffffffu, s, o);
        sq += __shfl_xor_sync(0xffffffffu, sq, o);
    }
    const float inv = 1.0f / 768.0f;
    float mean = s * inv;
    float var  = sq * inv - mean * mean;
    float rstd = rsqrtf(var + 1e-5f);

    float p0 = 0.f, p1 = 0.f, p2 = 0.f, p3 = 0.f;
    #pragma unroll
    for (int j = 0; j < 6; j++) {
        int idx = lane + 32 * j;
        float tx = v[j].x - mean, ty = v[j].y - mean, tz = v[j].z - mean, tw = v[j].w - mean;
        float4 u0 = u_s[idx];
        float4 u1 = u_s[E4 + idx];
        float4 u2 = u_s[2 * E4 + idx];
        float4 u3 = u_s[3 * E4 + idx];
        p0 += tx * u0.x + ty * u0.y + tz * u0.z + tw * u0.w;
        p1 += tx * u1.x + ty * u1.y + tz * u1.z + tw * u1.w;
        p2 += tx * u2.x + ty * u2.y + tz * u2.z + tw * u2.w;
        p3 += tx * u3.x + ty * u3.y + tz * u3.z + tw * u3.w;
    }
    #pragma unroll
    for (int o = 16; o; o >>= 1) {
        p0 += __shfl_xor_sync(0xffffffffu, p0, o);
        p1 += __shfl_xor_sync(0xffffffffu, p1, o);
        p2 += __shfl_xor_sync(0xffffffffu, p2, o);
        p3 += __shfl_xor_sync(0xffffffffu, p3, o);
    }
    if (lane == 0) {
        g_mu[row] = mean;
        g_rstd[row] = rstd;
        float* yd = &g_ydot[row * 4];
        yd[0] = p0 * rstd; yd[1] = p1 * rstd; yd[2] = p2 * rstd; yd[3] = p3 * rstd;
    }
}

// ---------------- kernel C: per n: softmax over k (4 heads), weighted sum of yhat
__global__ __launch_bounds__(192) void ypass2(const float* __restrict__ y,
                                              const float* __restrict__ gamma,
                                              const float* __restrict__ beta) {
    __shared__ float yd_s[K_NB * H_NUM];   // [k][h]
    __shared__ float w_s[H_NUM][K_NB];     // prob * rstd
    __shared__ float mu_s[K_NB], rs_s[K_NB];
    __shared__ float csub[H_NUM];          // sum_k w*mu

    int n = blockIdx.x;
    int tid = threadIdx.x;

    for (int i = tid; i < K_NB * H_NUM; i += blockDim.x) yd_s[i] = g_ydot[n * (K_NB * H_NUM) + i];
    if (tid < K_NB) mu_s[tid] = g_mu[n * K_NB + tid];
    if (tid >= 64 && tid < 64 + K_NB) rs_s[tid - 64] = g_rstd[n * K_NB + (tid - 64)];
    __syncthreads();

    int warp = tid >> 5, lane = tid & 31;
    if (warp < H_NUM) {
        int h = warp;
        float l1 = (lane < K_NB) ? yd_s[lane * 4 + h] : -1e30f;
        float l2 = (lane < K_NB - 32) ? yd_s[(lane + 32) * 4 + h] : -1e30f;
        float m = fmaxf(l1, l2);
        #pragma unroll
        for (int o = 16; o; o >>= 1) m = fmaxf(m, __shfl_xor_sync(0xffffffffu, m, o));
        float e1 = (lane < K_NB) ? expf(l1 - m) : 0.f;
        float e2 = (lane < K_NB - 32) ? expf(l2 - m) : 0.f;
        float se = e1 + e2;
        #pragma unroll
        for (int o = 16; o; o >>= 1) se += __shfl_xor_sync(0xffffffffu, se, o);
        float invs = 1.0f / se;
        float wv1 = 0.f, wv2 = 0.f;
        if (lane < K_NB)      { wv1 = e1 * invs * rs_s[lane];      w_s[h][lane]      = wv1; }
        if (lane < K_NB - 32) { wv2 = e2 * invs * rs_s[lane + 32]; w_s[h][lane + 32] = wv2; }
        float cp = (lane < K_NB ? wv1 * mu_s[lane] : 0.f) +
                   (lane < K_NB - 32 ? wv2 * mu_s[lane + 32] : 0.f);
        #pragma unroll
        for (int o = 16; o; o >>= 1) cp += __shfl_xor_sync(0xffffffffu, cp, o);
        if (lane == 0) csub[h] = cp;
    }
    __syncthreads();

    float4 acc[H_NUM];
    #pragma unroll
    for (int h = 0; h < H_NUM; h++) { acc[h].x = 0.f; acc[h].y = 0.f; acc[h].z = 0.f; acc[h].w = 0.f; }

    const float4* yb = (const float4*)y + (long)n * K_NB * E4;
    #pragma unroll 4
    for (int k = 0; k < K_NB; k++) {
        float4 v = yb[k * E4 + tid];
        #pragma unroll
        for (int h = 0; h < H_NUM; h++) {
            float w = w_s[h][k];
            acc[h].x += w * v.x; acc[h].y += w * v.y;
            acc[h].z += w * v.z; acc[h].w += w * v.w;
        }
    }
    #pragma unroll
    for (int h = 0; h < H_NUM; h++) {
        float4 ga = ((const float4*)gamma)[h * E4 + tid];
        float4 be = ((const float4*)beta)[h * E4 + tid];
        float c = csub[h];
        float4 o;
        o.x = (acc[h].x - c) * ga.x + be.x;
        o.y = (acc[h].y - c) * ga.y + be.y;
        o.z = (acc[h].z - c) * ga.z + be.z;
        o.w = (acc[h].w - c) * ga.w + be.w;
        ((float4*)g_gbuf)[((long)h * BS_TOT + n) * E4 + tid] = o;
    }
}

// ---------------- fused GEMM: C = epi(A @ B + bias, addsrc)
// MODE 0: out = GELU(add + acc + bias)   (head output -> cat)
// MODE 1: out = add + GELU(acc + bias)   (final residual)
#define BM 128
#define BN 64
#define BK 16
template <int MODE>
__global__ __launch_bounds__(256) void gemm_epi(
    const float* __restrict__ A, long aBatch, int lda,
    const float* __restrict__ B, long bBatch, int ldb,
    const float* __restrict__ bias, int biasBatch,
    const float* __restrict__ addsrc,
    float* __restrict__ C, int ldc, int colBatch,
    int K) {
    __shared__ __align__(16) float As[BK][BM + 4];
    __shared__ __align__(16) float Bs[BK][BN];

    int z = blockIdx.z;
    A += (long)z * aBatch;
    B += (long)z * bBatch;
    bias += (long)z * biasBatch;
    int coloff = z * colBatch;

    int m0 = blockIdx.y * BM, n0 = blockIdx.x * BN;
    int tid = threadIdx.x;
    int tm = tid >> 4, tn = tid & 15;
    int aRow = tid >> 2, aCol = (tid & 3) << 2;
    int bRow = tid >> 4, bCol = (tid & 15) << 2;

    float acc[8][4];
    #pragma unroll
    for (int i = 0; i < 8; i++)
        #pragma unroll
        for (int j = 0; j < 4; j++) acc[i][j] = 0.f;

    for (int kt = 0; kt < K; kt += BK) {
        float4 a0 = *(const float4*)(A + (long)(m0 + aRow) * lda + kt + aCol);
        float4 a1 = *(const float4*)(A + (long)(m0 + aRow + 64) * lda + kt + aCol);
        float4 b0 = *(const float4*)(B + (long)(kt + bRow) * ldb + n0 + bCol);
        __syncthreads();
        As[aCol + 0][aRow] = a0.x; As[aCol + 1][aRow] = a0.y;
        As[aCol + 2][aRow] = a0.z; As[aCol + 3][aRow] = a0.w;
        As[aCol + 0][aRow + 64] = a1.x; As[aCol + 1][aRow + 64] = a1.y;
        As[aCol + 2][aRow + 64] = a1.z; As[aCol + 3][aRow + 64] = a1.w;
        *(float4*)&Bs[bRow][bCol] = b0;
        __syncthreads();
        #pragma unroll
        for (int kk = 0; kk < BK; kk++) {
            float4 af0 = *(const float4*)&As[kk][tm * 8];
            float4 af1 = *(const float4*)&As[kk][tm * 8 + 4];
            float4 bf  = *(const float4*)&Bs[kk][tn * 4];
            float ar[8] = {af0.x, af0.y, af0.z, af0.w, af1.x, af1.y, af1.z, af1.w};
            float br[4] = {bf.x, bf.y, bf.z, bf.w};
            #pragma unroll
            for (int i = 0; i < 8; i++)
                #pragma unroll
                for (int j = 0; j < 4; j++) acc[i][j] += ar[i] * br[j];
        }
    }

    #pragma unroll
    for (int i = 0; i < 8; i++) {
        int row = m0 + tm * 8 + i;
        const float* addrow = addsrc + (long)row * E_DIM;
        float* crow = C + (long)row * ldc + coloff;
        #pragma unroll
        for (int j = 0; j < 4; j++) {
            int col = n0 + tn * 4 + j;
            float v = acc[i][j];
            float o;
            if (MODE == 0) o = gelu_tanh(addrow[col] + v + bias[col]);
            else           o = addrow[col] + gelu_tanh(v + bias[col]);
            crow[col] = o;
        }
    }
}

// ---------------- launch ----------------
extern "C" void kernel_launch(void* const* d_in, const int* in_sizes, int n_in,
                              void* d_out, int out_size) {
    (void)in_sizes; (void)n_in; (void)out_size;
    const float* x     = (const float*)d_in[0];   // [2048,768]
    const float* y     = (const float*)d_in[1];   // [2048,36,768]
    const float* gamma = (const float*)d_in[2];   // [4,768]
    const float* beta  = (const float*)d_in[3];   // [4,768]
    const float* W1    = (const float*)d_in[4];   // [4,768,768]
    const float* b1    = (const float*)d_in[5];   // [4,768]
    // d_in[6] = W2x, d_in[8] = b2: provably cancel in the softmax — unused.
    const float* W2y   = (const float*)d_in[7];   // [4,768]
    const float* Wm    = (const float*)d_in[9];   // [3072,768]
    const float* bm    = (const float*)d_in[10];  // [768]
    float* out = (float*)d_out;

    float *p_g = nullptr, *p_cat = nullptr;
    cudaGetSymbolAddress((void**)&p_g, g_gbuf);
    cudaGetSymbolAddress((void**)&p_cat, g_cat);

    prep_u<<<384, 256>>>(W1, W2y, gamma);
    ypass1<<<(BS_TOT * K_NB) / 8, 256>>>(y);
    ypass2<<<BS_TOT, 192>>>(y, gamma, beta);
    // head GEMMs: cat[:, h*768+e] = GELU(x + g_h @ W1[h] + b1[h])
    gemm_epi<0><<<dim3(E_DIM / BN, BS_TOT / BM, H_NUM), 256>>>(
        p_g, (long)BS_TOT * E_DIM, E_DIM,
        W1, (long)E_DIM * E_DIM, E_DIM,
        b1, E_DIM, x,
        p_cat, H_NUM * E_DIM, E_DIM, E_DIM);
    // final: out = x + GELU(cat @ Wm + bm)
    gemm_epi<1><<<dim3(E_DIM / BN, BS_TOT / BM, 1), 256>>>(
        p_cat, 0, H_NUM * E_DIM,
        Wm, 0, E_DIM,
        bm, 0, x,
        out, E_DIM, 0, H_NUM * E_DIM);
}

// round 3
// speedup vs baseline: 1.9312x; 1.9312x over previous
#include <cuda_runtime.h>
#include <cuda_bf16.h>
#include <cstdint>

// Problem constants (fixed by setup_inputs)
#define BS_TOT 2048      // B*S
#define E_DIM  768
#define E4     192       // E/4
#define K_NB   36
#define H_NUM  4
#define CATD   (H_NUM * E_DIM)   // 3072

// ---------------- scratch (device globals; no allocations) ----------------
__device__ float g_u[H_NUM * E_DIM];                    // gamma ⊙ (W1 @ W2y)
__device__ float g_ydot[BS_TOT * K_NB * H_NUM];         // yhat·u per (n,k,h)
__device__ float g_mu[BS_TOT * K_NB];
__device__ float g_rstd[BS_TOT * K_NB];

// bf16 split buffers for HMMA GEMMs
__device__ __nv_bfloat16 g_a_hi[(long)H_NUM * BS_TOT * E_DIM];
__device__ __nv_bfloat16 g_a_lo[(long)H_NUM * BS_TOT * E_DIM];
__device__ __nv_bfloat16 g_w1t_hi[(long)H_NUM * E_DIM * E_DIM];
__device__ __nv_bfloat16 g_w1t_lo[(long)H_NUM * E_DIM * E_DIM];
__device__ __nv_bfloat16 g_cat_hi[(long)BS_TOT * CATD];
__device__ __nv_bfloat16 g_cat_lo[(long)BS_TOT * CATD];
__device__ __nv_bfloat16 g_wmt_hi[(long)E_DIM * CATD];
__device__ __nv_bfloat16 g_wmt_lo[(long)E_DIM * CATD];

__device__ __forceinline__ float gelu_tanh(float v) {
    const float c = 0.7978845608028654f;   // sqrt(2/pi)
    float t = tanhf(c * (v + 0.044715f * v * v * v));
    return 0.5f * v * (1.0f + t);
}

__device__ __forceinline__ void bf16_split(float v, __nv_bfloat16& hi, __nv_bfloat16& lo) {
    hi = __float2bfloat16(v);
    lo = __float2bfloat16(v - __bfloat162float(hi));
}

__device__ __forceinline__ uint32_t smem_u32(const void* p) {
    uint32_t a;
    asm("{ .reg .u64 t; cvta.to.shared.u64 t, %1; cvt.u32.u64 %0, t; }" : "=r"(a) : "l"(p));
    return a;
}

#define CP_ASYNC16(sm, gm) \
    asm volatile("cp.async.cg.shared.global [%0], [%1], 16;" :: "r"(sm), "l"(gm))
#define CP_COMMIT() asm volatile("cp.async.commit_group;" ::: "memory")
#define CP_WAIT(n)  asm volatile("cp.async.wait_group %0;" :: "n"(n) : "memory")

#define LDSM_X4(r0, r1, r2, r3, a) \
    asm volatile("ldmatrix.sync.aligned.m8n8.x4.shared.b16 {%0,%1,%2,%3}, [%4];" \
                 : "=r"(r0), "=r"(r1), "=r"(r2), "=r"(r3) : "r"(a))

#define MMA16816(d, a, b0v, b1v) \
    asm volatile("mma.sync.aligned.m16n8k16.row.col.f32.bf16.bf16.f32 " \
                 "{%0,%1,%2,%3}, {%4,%5,%6,%7}, {%8,%9}, {%0,%1,%2,%3};" \
                 : "+f"((d)[0]), "+f"((d)[1]), "+f"((d)[2]), "+f"((d)[3]) \
                 : "r"((a)[0]), "r"((a)[1]), "r"((a)[2]), "r"((a)[3]), \
                   "r"(b0v), "r"(b1v))

// ---------------- kernel P: u[h][i] = gamma[h][i] * sum_j W1[h][i][j]*W2y[h][j]
__global__ void prep_u(const float* __restrict__ W1,
                       const float* __restrict__ W2y,
                       const float* __restrict__ gamma) {
    int warp = (blockIdx.x * blockDim.x + threadIdx.x) >> 5;
    int lane = threadIdx.x & 31;
    if (warp >= H_NUM * E_DIM) return;
    int h = warp / E_DIM;
    const float* wrow = W1 + (long)warp * E_DIM;
    const float* w2 = W2y + h * E_DIM;
    float s = 0.f;
    #pragma unroll 4
    for (int j = lane; j < E_DIM; j += 32) s += wrow[j] * w2[j];
    #pragma unroll
    for (int o = 16; o; o >>= 1) s += __shfl_xor_sync(0xffffffffu, s, o);
    if (lane == 0) g_u[warp] = gamma[warp] * s;
}

// ---------------- transpose + bf16 split: out[n][k] = split(in[k][n])
__global__ void transpose_split(const float* __restrict__ in, int K, int N, long inBatch,
                                __nv_bfloat16* __restrict__ oh,
                                __nv_bfloat16* __restrict__ ol, long outBatch) {
    __shared__ float t[32][33];
    int z = blockIdx.z;
    in += (long)z * inBatch;
    oh += (long)z * outBatch;
    ol += (long)z * outBatch;
    int k0 = blockIdx.x * 32, n0 = blockIdx.y * 32;
    for (int i = threadIdx.y; i < 32; i += 8)
        t[i][threadIdx.x] = in[(long)(k0 + i) * N + n0 + threadIdx.x];
    __syncthreads();
    for (int i = threadIdx.y; i < 32; i += 8) {
        float v = t[threadIdx.x][i];
        __nv_bfloat16 hi, lo;
        bf16_split(v, hi, lo);
        long o = (long)(n0 + i) * K + k0 + threadIdx.x;
        oh[o] = hi;
        ol[o] = lo;
    }
}

// ---------------- kernel A: per (n,k) row of y: mean, rstd, 4 dots with u[h]
__global__ __launch_bounds__(256) void ypass1(const float* __restrict__ y) {
    __shared__ float4 u_s[H_NUM * E4];
    const float4* u4 = (const float4*)g_u;
    for (int i = threadIdx.x; i < H_NUM * E4; i += blockDim.x) u_s[i] = u4[i];
    __syncthreads();

    int warp = threadIdx.x >> 5, lane = threadIdx.x & 31;
    int row = blockIdx.x * 8 + warp;
    const float4* yr = (const float4*)y + (long)row * E4;

    float4 v[6];
    float s = 0.f, sq = 0.f;
    #pragma unroll
    for (int j = 0; j < 6; j++) {
        v[j] = yr[lane + 32 * j];
        s  += v[j].x + v[j].y + v[j].z + v[j].w;
        sq += v[j].x * v[j].x + v[j].y * v[j].y + v[j].z * v[j].z + v[j].w * v[j].w;
    }
    #pragma unroll
    for (int o = 16; o; o >>= 1) {
        s  += __shfl_xor_sync(0xffffffffu, s, o);
        sq += __shfl_xor_sync(0xffffffffu, sq, o);
    }
    const float inv = 1.0f / 768.0f;
    float mean = s * inv;
    float var  = sq * inv - mean * mean;
    float rstd = rsqrtf(var + 1e-5f);

    float p0 = 0.f, p1 = 0.f, p2 = 0.f, p3 = 0.f;
    #pragma unroll
    for (int j = 0; j < 6; j++) {
        int idx = lane + 32 * j;
        float tx = v[j].x - mean, ty = v[j].y - mean, tz = v[j].z - mean, tw = v[j].w - mean;
        float4 u0 = u_s[idx];
        float4 u1 = u_s[E4 + idx];
        float4 u2 = u_s[2 * E4 + idx];
        float4 u3 = u_s[3 * E4 + idx];
        p0 += tx * u0.x + ty * u0.y + tz * u0.z + tw * u0.w;
        p1 += tx * u1.x + ty * u1.y + tz * u1.z + tw * u1.w;
        p2 += tx * u2.x + ty * u2.y + tz * u2.z + tw * u2.w;
        p3 += tx * u3.x + ty * u3.y + tz * u3.z + tw * u3.w;
    }
    #pragma unroll
    for (int o = 16; o; o >>= 1) {
        p0 += __shfl_xor_sync(0xffffffffu, p0, o);
        p1 += __shfl_xor_sync(0xffffffffu, p1, o);
        p2 += __shfl_xor_sync(0xffffffffu, p2, o);
        p3 += __shfl_xor_sync(0xffffffffu, p3, o);
    }
    if (lane == 0) {
        g_mu[row] = mean;
        g_rstd[row] = rstd;
        float* yd = &g_ydot[row * 4];
        yd[0] = p0 * rstd; yd[1] = p1 * rstd; yd[2] = p2 * rstd; yd[3] = p3 * rstd;
    }
}

// ---------------- kernel C: softmax over k (4 heads), weighted sum -> bf16 split A
__global__ __launch_bounds__(192) void ypass2(const float* __restrict__ y,
                                              const float* __restrict__ gamma,
                                              const float* __restrict__ beta) {
    __shared__ float yd_s[K_NB * H_NUM];
    __shared__ float w_s[H_NUM][K_NB];
    __shared__ float mu_s[K_NB], rs_s[K_NB];
    __shared__ float csub[H_NUM];

    int n = blockIdx.x;
    int tid = threadIdx.x;

    for (int i = tid; i < K_NB * H_NUM; i += blockDim.x) yd_s[i] = g_ydot[n * (K_NB * H_NUM) + i];
    if (tid < K_NB) mu_s[tid] = g_mu[n * K_NB + tid];
    if (tid >= 64 && tid < 64 + K_NB) rs_s[tid - 64] = g_rstd[n * K_NB + (tid - 64)];
    __syncthreads();

    int warp = tid >> 5, lane = tid & 31;
    if (warp < H_NUM) {
        int h = warp;
        float l1 = (lane < K_NB) ? yd_s[lane * 4 + h] : -1e30f;
        float l2 = (lane < K_NB - 32) ? yd_s[(lane + 32) * 4 + h] : -1e30f;
        float m = fmaxf(l1, l2);
        #pragma unroll
        for (int o = 16; o; o >>= 1) m = fmaxf(m, __shfl_xor_sync(0xffffffffu, m, o));
        float e1 = (lane < K_NB) ? expf(l1 - m) : 0.f;
        float e2 = (lane < K_NB - 32) ? expf(l2 - m) : 0.f;
        float se = e1 + e2;
        #pragma unroll
        for (int o = 16; o; o >>= 1) se += __shfl_xor_sync(0xffffffffu, se, o);
        float invs = 1.0f / se;
        float wv1 = 0.f, wv2 = 0.f;
        if (lane < K_NB)      { wv1 = e1 * invs * rs_s[lane];      w_s[h][lane]      = wv1; }
        if (lane < K_NB - 32) { wv2 = e2 * invs * rs_s[lane + 32]; w_s[h][lane + 32] = wv2; }
        float cp = (lane < K_NB ? wv1 * mu_s[lane] : 0.f) +
                   (lane < K_NB - 32 ? wv2 * mu_s[lane + 32] : 0.f);
        #pragma unroll
        for (int o = 16; o; o >>= 1) cp += __shfl_xor_sync(0xffffffffu, cp, o);
        if (lane == 0) csub[h] = cp;
    }
    __syncthreads();

    float4 acc[H_NUM];
    #pragma unroll
    for (int h = 0; h < H_NUM; h++) { acc[h].x = 0.f; acc[h].y = 0.f; acc[h].z = 0.f; acc[h].w = 0.f; }

    const float4* yb = (const float4*)y + (long)n * K_NB * E4;
    #pragma unroll 4
    for (int k = 0; k < K_NB; k++) {
        float4 v = yb[k * E4 + tid];
        #pragma unroll
        for (int h = 0; h < H_NUM; h++) {
            float w = w_s[h][k];
            acc[h].x += w * v.x; acc[h].y += w * v.y;
            acc[h].z += w * v.z; acc[h].w += w * v.w;
        }
    }
    #pragma unroll
    for (int h = 0; h < H_NUM; h++) {
        float4 ga = ((const float4*)gamma)[h * E4 + tid];
        float4 be = ((const float4*)beta)[h * E4 + tid];
        float c = csub[h];
        float o0 = (acc[h].x - c) * ga.x + be.x;
        float o1 = (acc[h].y - c) * ga.y + be.y;
        float o2 = (acc[h].z - c) * ga.z + be.z;
        float o3 = (acc[h].w - c) * ga.w + be.w;
        long base = ((long)h * BS_TOT + n) * E_DIM + tid * 4;
        __nv_bfloat16 h0, h1, h2, h3, l0, l1, l2, l3;
        bf16_split(o0, h0, l0); bf16_split(o1, h1, l1);
        bf16_split(o2, h2, l2); bf16_split(o3, h3, l3);
        __nv_bfloat162* ph = (__nv_bfloat162*)(g_a_hi + base);
        __nv_bfloat162* pl = (__nv_bfloat162*)(g_a_lo + base);
        ph[0] = __halves2bfloat162(h0, h1); ph[1] = __halves2bfloat162(h2, h3);
        pl[0] = __halves2bfloat162(l0, l1); pl[1] = __halves2bfloat162(l2, l3);
    }
}

// ================= HMMA (mma.sync bf16) split GEMM =================
// D[m][n] = sum_k A[m][k]*B[n][k] via bf16-split 3-term HMMA, fp32 acc.
// MODE 0: cat_hi/lo[m][coloff+n] = split(GELU(x[m][n] + D + bias[n]))
// MODE 1: outF[m][n] = x[m][n] + GELU(D + bias[n])
#define TM 128
#define TN 128
#define KC 32
// per-stage buffers: rows padded to 40 bf16 (80B) for conflict-free LDSM
#define ROWB   80
#define BUF_SZ (128 * ROWB)          // 10240 B
#define SA_HI  0
#define SA_LO  (BUF_SZ)
#define SB_HI  (2 * BUF_SZ)
#define SB_LO  (3 * BUF_SZ)
#define STAGE  (4 * BUF_SZ)          // 40960 B
#define GEMM_SMEM (2 * STAGE)        // 81920 B

template <int MODE>
__global__ __launch_bounds__(256) void gemm_mma(
    const __nv_bfloat16* __restrict__ Ahi, const __nv_bfloat16* __restrict__ Alo,
    long aBatch, int lda,
    const __nv_bfloat16* __restrict__ Bhi, const __nv_bfloat16* __restrict__ Blo,
    long bBatch, int ldb,
    const float* __restrict__ bias, int biasBatch,
    const float* __restrict__ x,
    float* __restrict__ outF,
    __nv_bfloat16* __restrict__ outHi, __nv_bfloat16* __restrict__ outLo,
    int ldc, int colBatch, int K) {
    extern __shared__ char smem[];
    uint32_t sb = smem_u32(smem);
    const int tid = threadIdx.x, w = tid >> 5, l = tid & 31;

    int z = blockIdx.z;
    Ahi += (long)z * aBatch; Alo += (long)z * aBatch;
    Bhi += (long)z * bBatch; Blo += (long)z * bBatch;
    bias += (long)z * biasBatch;
    const int coloff = z * colBatch;
    const int m0 = blockIdx.y * TM, n0 = blockIdx.x * TN;
    const int wm = (w >> 2) * 64, wn = (w & 3) * 32;

    // gmem->smem: thread handles rows (tid>>2) and (tid>>2)+64, 16B chunk (tid&3)
    const int gr = tid >> 2, gc = tid & 3;
    const long aoff0 = ((long)(m0 + gr) * lda + gc * 8) * 2;
    const long aoff1 = aoff0 + (long)64 * lda * 2;
    const long boff0 = ((long)(n0 + gr) * ldb + gc * 8) * 2;
    const long boff1 = boff0 + (long)64 * ldb * 2;
    const uint32_t soff0 = gr * ROWB + gc * 16;
    const uint32_t soff1 = (gr + 64) * ROWB + gc * 16;
    const char* aH = (const char*)Ahi;
    const char* aL = (const char*)Alo;
    const char* bH = (const char*)Bhi;
    const char* bL = (const char*)Blo;

    // LDSM per-lane address components
    const uint32_t a_r = (l & 15) * ROWB + (l >> 4) * 16;                     // row + k-block
    const uint32_t b_r = (((l >> 4) & 1) * 8 + (l & 7)) * ROWB + ((l >> 3) & 1) * 16;

    float acc[4][4][4];
    #pragma unroll
    for (int i = 0; i < 4; i++)
        #pragma unroll
        for (int j = 0; j < 4; j++)
            #pragma unroll
            for (int q = 0; q < 4; q++) acc[i][j][q] = 0.f;

    const int NC = K / KC;

    // prologue: stage 0
    {
        uint32_t s0 = sb;
        long kb = 0;
        CP_ASYNC16(s0 + SA_HI + soff0, aH + aoff0 + kb);
        CP_ASYNC16(s0 + SA_HI + soff1, aH + aoff1 + kb);
        CP_ASYNC16(s0 + SA_LO + soff0, aL + aoff0 + kb);
        CP_ASYNC16(s0 + SA_LO + soff1, aL + aoff1 + kb);
        CP_ASYNC16(s0 + SB_HI + soff0, bH + boff0 + kb);
        CP_ASYNC16(s0 + SB_HI + soff1, bH + boff1 + kb);
        CP_ASYNC16(s0 + SB_LO + soff0, bL + boff0 + kb);
        CP_ASYNC16(s0 + SB_LO + soff1, bL + boff1 + kb);
        CP_COMMIT();
    }

    for (int c = 0; c < NC; c++) {
        if (c + 1 < NC) {
            uint32_t sn = sb + ((c + 1) & 1) * STAGE;
            long kb = (long)(c + 1) * KC * 2;
            CP_ASYNC16(sn + SA_HI + soff0, aH + aoff0 + kb);
            CP_ASYNC16(sn + SA_HI + soff1, aH + aoff1 + kb);
            CP_ASYNC16(sn + SA_LO + soff0, aL + aoff0 + kb);
            CP_ASYNC16(sn + SA_LO + soff1, aL + aoff1 + kb);
            CP_ASYNC16(sn + SB_HI + soff0, bH + boff0 + kb);
            CP_ASYNC16(sn + SB_HI + soff1, bH + boff1 + kb);
            CP_ASYNC16(sn + SB_LO + soff0, bL + boff0 + kb);
            CP_ASYNC16(sn + SB_LO + soff1, bL + boff1 + kb);
            CP_COMMIT();
            CP_WAIT(1);
        } else {
            CP_WAIT(0);
        }
        __syncthreads();

        uint32_t st = sb + (c & 1) * STAGE;
        #pragma unroll
        for (int kk = 0; kk < 2; kk++) {
            uint32_t kby = kk * 32;   // 16 bf16 = 32B
            uint32_t ah[4][4], al[4][4], bh[2][4], bl[2][4];
            #pragma unroll
            for (int mt = 0; mt < 4; mt++) {
                uint32_t ra = st + SA_HI + (wm + mt * 16) * ROWB + a_r + kby;
                LDSM_X4(ah[mt][0], ah[mt][1], ah[mt][2], ah[mt][3], ra);
                uint32_t rl = st + SA_LO + (wm + mt * 16) * ROWB + a_r + kby;
                LDSM_X4(al[mt][0], al[mt][1], al[mt][2], al[mt][3], rl);
            }
            #pragma unroll
            for (int np = 0; np < 2; np++) {
                uint32_t rb = st + SB_HI + (wn + np * 16) * ROWB + b_r + kby;
                LDSM_X4(bh[np][0], bh[np][1], bh[np][2], bh[np][3], rb);
                uint32_t rc = st + SB_LO + (wn + np * 16) * ROWB + b_r + kby;
                LDSM_X4(bl[np][0], bl[np][1], bl[np][2], bl[np][3], rc);
            }
            #pragma unroll
            for (int mt = 0; mt < 4; mt++) {
                #pragma unroll
                for (int nt = 0; nt < 4; nt++) {
                    uint32_t bh0 = bh[nt >> 1][(nt & 1) * 2];
                    uint32_t bh1 = bh[nt >> 1][(nt & 1) * 2 + 1];
                    uint32_t bl0 = bl[nt >> 1][(nt & 1) * 2];
                    uint32_t bl1 = bl[nt >> 1][(nt & 1) * 2 + 1];
                    MMA16816(acc[mt][nt], ah[mt], bh0, bh1);
                    MMA16816(acc[mt][nt], ah[mt], bl0, bl1);
                    MMA16816(acc[mt][nt], al[mt], bh0, bh1);
                }
            }
        }
        __syncthreads();
    }

    // epilogue: thread holds (mt,nt) -> rows m0+wm+mt*16+(l>>2) (+8), cols n0+wn+nt*8+2*(l&3) (+1)
    #pragma unroll
    for (int mt = 0; mt < 4; mt++) {
        #pragma unroll
        for (int nt = 0; nt < 4; nt++) {
            int row0 = m0 + wm + mt * 16 + (l >> 2);
            int col = n0 + wn + nt * 8 + ((l & 3) << 1);
            #pragma unroll
            for (int rh = 0; rh < 2; rh++) {
                int row = row0 + rh * 8;
                float d0 = acc[mt][nt][rh * 2 + 0];
                float d1 = acc[mt][nt][rh * 2 + 1];
                float2 xv = *(const float2*)(x + (long)row * E_DIM + col);
                float2 bv = *(const float2*)(bias + col);
                if (MODE == 0) {
                    float o0 = gelu_tanh(xv.x + d0 + bv.x);
                    float o1 = gelu_tanh(xv.y + d1 + bv.y);
                    __nv_bfloat16 h0, h1, l0v, l1v;
                    bf16_split(o0, h0, l0v);
                    bf16_split(o1, h1, l1v);
                    long cb = (long)row * ldc + coloff + col;
                    *(__nv_bfloat162*)(outHi + cb) = __halves2bfloat162(h0, h1);
                    *(__nv_bfloat162*)(outLo + cb) = __halves2bfloat162(l0v, l1v);
                } else {
                    float2 o;
                    o.x = xv.x + gelu_tanh(d0 + bv.x);
                    o.y = xv.y + gelu_tanh(d1 + bv.y);
                    *(float2*)(outF + (long)row * ldc + col) = o;
                }
            }
        }
    }
}

// ---------------- launch ----------------
extern "C" void kernel_launch(void* const* d_in, const int* in_sizes, int n_in,
                              void* d_out, int out_size) {
    (void)in_sizes; (void)n_in; (void)out_size;
    const float* x     = (const float*)d_in[0];   // [2048,768]
    const float* y     = (const float*)d_in[1];   // [2048,36,768]
    const float* gamma = (const float*)d_in[2];   // [4,768]
    const float* beta  = (const float*)d_in[3];   // [4,768]
    const float* W1    = (const float*)d_in[4];   // [4,768,768]
    const float* b1    = (const float*)d_in[5];   // [4,768]
    // d_in[6] = W2x, d_in[8] = b2: cancel in the softmax — unused.
    const float* W2y   = (const float*)d_in[7];   // [4,768]
    const float* Wm    = (const float*)d_in[9];   // [3072,768]
    const float* bm    = (const float*)d_in[10];  // [768]
    float* out = (float*)d_out;

    __nv_bfloat16 *p_a_hi, *p_a_lo, *p_w1t_hi, *p_w1t_lo, *p_cat_hi, *p_cat_lo, *p_wmt_hi, *p_wmt_lo;
    cudaGetSymbolAddress((void**)&p_a_hi, g_a_hi);
    cudaGetSymbolAddress((void**)&p_a_lo, g_a_lo);
    cudaGetSymbolAddress((void**)&p_w1t_hi, g_w1t_hi);
    cudaGetSymbolAddress((void**)&p_w1t_lo, g_w1t_lo);
    cudaGetSymbolAddress((void**)&p_cat_hi, g_cat_hi);
    cudaGetSymbolAddress((void**)&p_cat_lo, g_cat_lo);
    cudaGetSymbolAddress((void**)&p_wmt_hi, g_wmt_hi);
    cudaGetSymbolAddress((void**)&p_wmt_lo, g_wmt_lo);

    cudaFuncSetAttribute(gemm_mma<0>, cudaFuncAttributeMaxDynamicSharedMemorySize, GEMM_SMEM);
    cudaFuncSetAttribute(gemm_mma<1>, cudaFuncAttributeMaxDynamicSharedMemorySize, GEMM_SMEM);

    prep_u<<<384, 256>>>(W1, W2y, gamma);
    transpose_split<<<dim3(24, 24, 4), dim3(32, 8)>>>(W1, 768, 768, 768L * 768,
                                                      p_w1t_hi, p_w1t_lo, 768L * 768);
    transpose_split<<<dim3(96, 24, 1), dim3(32, 8)>>>(Wm, 3072, 768, 0,
                                                      p_wmt_hi, p_wmt_lo, 0);
    ypass1<<<(BS_TOT * K_NB) / 8, 256>>>(y);
    ypass2<<<BS_TOT, 192>>>(y, gamma, beta);

    // GEMM1 (per head): cat[:, h*768+n] = GELU(x + A_h @ W1[h]^T + b1[h])
    gemm_mma<0><<<dim3(E_DIM / TN, BS_TOT / TM, H_NUM), 256, GEMM_SMEM>>>(
        p_a_hi, p_a_lo, (long)BS_TOT * E_DIM, E_DIM,
        p_w1t_hi, p_w1t_lo, (long)E_DIM * E_DIM, E_DIM,
        b1, E_DIM, x,
        nullptr, p_cat_hi, p_cat_lo, CATD, E_DIM, E_DIM);
    // GEMM2: out = x + GELU(cat @ WmT^T + bm)
    gemm_mma<1><<<dim3(E_DIM / TN, BS_TOT / TM, 1), 256, GEMM_SMEM>>>(
        p_cat_hi, p_cat_lo, 0, CATD,
        p_wmt_hi, p_wmt_lo, 0, CATD,
        bm, 0, x,
        out, nullptr, nullptr, E_DIM, 0, CATD);
}

// round 4
// speedup vs baseline: 2.0662x; 1.0699x over previous
#include <cuda_runtime.h>
#include <cuda_bf16.h>
#include <cstdint>

// Problem constants (fixed by setup_inputs)
#define BS_TOT 2048      // B*S
#define E_DIM  768
#define E4     192       // E/4
#define K_NB   36
#define H_NUM  4
#define CATD   (H_NUM * E_DIM)   // 3072

// ---------------- scratch (device globals; no allocations) ----------------
__device__ float g_u[H_NUM * E_DIM];                    // gamma ⊙ (W1 @ W2y)

// bf16 split buffers for HMMA GEMMs
__device__ __nv_bfloat16 g_a_hi[(long)H_NUM * BS_TOT * E_DIM];
__device__ __nv_bfloat16 g_a_lo[(long)H_NUM * BS_TOT * E_DIM];
__device__ __nv_bfloat16 g_w1t_hi[(long)H_NUM * E_DIM * E_DIM];
__device__ __nv_bfloat16 g_w1t_lo[(long)H_NUM * E_DIM * E_DIM];
__device__ __nv_bfloat16 g_cat_hi[(long)BS_TOT * CATD];
__device__ __nv_bfloat16 g_cat_lo[(long)BS_TOT * CATD];
__device__ __nv_bfloat16 g_wmt_hi[(long)E_DIM * CATD];
__device__ __nv_bfloat16 g_wmt_lo[(long)E_DIM * CATD];

__device__ __forceinline__ float gelu_tanh(float v) {
    const float c = 0.7978845608028654f;   // sqrt(2/pi)
    float t = tanhf(c * (v + 0.044715f * v * v * v));
    return 0.5f * v * (1.0f + t);
}

__device__ __forceinline__ void bf16_split(float v, __nv_bfloat16& hi, __nv_bfloat16& lo) {
    hi = __float2bfloat16(v);
    lo = __float2bfloat16(v - __bfloat162float(hi));
}

__device__ __forceinline__ uint32_t smem_u32(const void* p) {
    uint32_t a;
    asm("{ .reg .u64 t; cvta.to.shared.u64 t, %1; cvt.u32.u64 %0, t; }" : "=r"(a) : "l"(p));
    return a;
}

#define CP_ASYNC16(sm, gm) \
    asm volatile("cp.async.cg.shared.global [%0], [%1], 16;" :: "r"(sm), "l"(gm))
#define CP_COMMIT() asm volatile("cp.async.commit_group;" ::: "memory")
#define CP_WAIT(n)  asm volatile("cp.async.wait_group %0;" :: "n"(n) : "memory")

#define LDSM_X4(r0, r1, r2, r3, a) \
    asm volatile("ldmatrix.sync.aligned.m8n8.x4.shared.b16 {%0,%1,%2,%3}, [%4];" \
                 : "=r"(r0), "=r"(r1), "=r"(r2), "=r"(r3) : "r"(a))

#define MMA16816(d, a, b0v, b1v) \
    asm volatile("mma.sync.aligned.m16n8k16.row.col.f32.bf16.bf16.f32 " \
                 "{%0,%1,%2,%3}, {%4,%5,%6,%7}, {%8,%9}, {%0,%1,%2,%3};" \
                 : "+f"((d)[0]), "+f"((d)[1]), "+f"((d)[2]), "+f"((d)[3]) \
                 : "r"((a)[0]), "r"((a)[1]), "r"((a)[2]), "r"((a)[3]), \
                   "r"(b0v), "r"(b1v))

// ---------------- kernel P: u[h][i] = gamma[h][i] * sum_j W1[h][i][j]*W2y[h][j]
__global__ void prep_u(const float* __restrict__ W1,
                       const float* __restrict__ W2y,
                       const float* __restrict__ gamma) {
    int warp = (blockIdx.x * blockDim.x + threadIdx.x) >> 5;
    int lane = threadIdx.x & 31;
    if (warp >= H_NUM * E_DIM) return;
    int h = warp / E_DIM;
    const float* wrow = W1 + (long)warp * E_DIM;
    const float* w2 = W2y + h * E_DIM;
    float s = 0.f;
    #pragma unroll 4
    for (int j = lane; j < E_DIM; j += 32) s += wrow[j] * w2[j];
    #pragma unroll
    for (int o = 16; o; o >>= 1) s += __shfl_xor_sync(0xffffffffu, s, o);
    if (lane == 0) g_u[warp] = gamma[warp] * s;
}

// ---------------- transpose + bf16 split: out[n][k] = split(in[k][n])
__global__ void transpose_split(const float* __restrict__ in, int K, int N, long inBatch,
                                __nv_bfloat16* __restrict__ oh,
                                __nv_bfloat16* __restrict__ ol, long outBatch) {
    __shared__ float t[32][33];
    int z = blockIdx.z;
    in += (long)z * inBatch;
    oh += (long)z * outBatch;
    ol += (long)z * outBatch;
    int k0 = blockIdx.x * 32, n0 = blockIdx.y * 32;
    for (int i = threadIdx.y; i < 32; i += 8)
        t[i][threadIdx.x] = in[(long)(k0 + i) * N + n0 + threadIdx.x];
    __syncthreads();
    for (int i = threadIdx.y; i < 32; i += 8) {
        float v = t[threadIdx.x][i];
        __nv_bfloat16 hi, lo;
        bf16_split(v, hi, lo);
        long o = (long)(n0 + i) * K + k0 + threadIdx.x;
        oh[o] = hi;
        ol[o] = lo;
    }
}

// ---------------- fused y kernel: one CTA per token n ----------------
// Phase 1: per-row (k) LN stats + dots with u[h]  (reads y[n], 110KB, DRAM)
// Phase 2: softmax over k per head (pure smem)
// Phase 3: weighted sum over k (re-reads y[n], expected L2-hot) -> bf16 split A
__global__ __launch_bounds__(256) void fused_y(const float* __restrict__ y,
                                               const float* __restrict__ gamma,
                                               const float* __restrict__ beta) {
    __shared__ float4 u_s[H_NUM * E4];     // 12 KB
    __shared__ float yd_s[K_NB * 4];       // dots*rstd, [k][h]
    __shared__ float mu_s[K_NB];
    __shared__ float rs_s[K_NB];
    __shared__ float w_s[H_NUM][K_NB];     // prob * rstd
    __shared__ float csub[H_NUM];

    const int n = blockIdx.x;
    const int tid = threadIdx.x;
    const int w = tid >> 5, lane = tid & 31;

    const float4* u4 = (const float4*)g_u;
    for (int i = tid; i < H_NUM * E4; i += 256) u_s[i] = u4[i];
    __syncthreads();

    const float4* yb = (const float4*)y + (long)n * K_NB * E4;

    // ---- phase 1: rows k = w, w+8, ... ----
    for (int k = w; k < K_NB; k += 8) {
        const float4* yr = yb + (long)k * E4;
        float4 v[6];
        float s = 0.f, sq = 0.f;
        #pragma unroll
        for (int j = 0; j < 6; j++) {
            v[j] = yr[lane + 32 * j];
            s  += v[j].x + v[j].y + v[j].z + v[j].w;
            sq += v[j].x * v[j].x + v[j].y * v[j].y + v[j].z * v[j].z + v[j].w * v[j].w;
        }
        #pragma unroll
        for (int o = 16; o; o >>= 1) {
            s  += __shfl_xor_sync(0xffffffffu, s, o);
            sq += __shfl_xor_sync(0xffffffffu, sq, o);
        }
        const float inv = 1.0f / 768.0f;
        float mean = s * inv;
        float var  = sq * inv - mean * mean;
        float rstd = rsqrtf(var + 1e-5f);

        float p0 = 0.f, p1 = 0.f, p2 = 0.f, p3 = 0.f;
        #pragma unroll
        for (int j = 0; j < 6; j++) {
            int idx = lane + 32 * j;
            float tx = v[j].x - mean, ty = v[j].y - mean, tz = v[j].z - mean, tw = v[j].w - mean;
            float4 u0 = u_s[idx];
            float4 u1 = u_s[E4 + idx];
            float4 u2 = u_s[2 * E4 + idx];
            float4 u3 = u_s[3 * E4 + idx];
            p0 += tx * u0.x + ty * u0.y + tz * u0.z + tw * u0.w;
            p1 += tx * u1.x + ty * u1.y + tz * u1.z + tw * u1.w;
            p2 += tx * u2.x + ty * u2.y + tz * u2.z + tw * u2.w;
            p3 += tx * u3.x + ty * u3.y + tz * u3.z + tw * u3.w;
        }
        #pragma unroll
        for (int o = 16; o; o >>= 1) {
            p0 += __shfl_xor_sync(0xffffffffu, p0, o);
            p1 += __shfl_xor_sync(0xffffffffu, p1, o);
            p2 += __shfl_xor_sync(0xffffffffu, p2, o);
            p3 += __shfl_xor_sync(0xffffffffu, p3, o);
        }
        if (lane == 0) {
            mu_s[k] = mean;
            rs_s[k] = rstd;
            yd_s[k * 4 + 0] = p0 * rstd;
            yd_s[k * 4 + 1] = p1 * rstd;
            yd_s[k * 4 + 2] = p2 * rstd;
            yd_s[k * 4 + 3] = p3 * rstd;
        }
    }
    __syncthreads();

    // ---- phase 2: softmax per head (warps 0..3) ----
    if (w < H_NUM) {
        int h = w;
        float l1 = (lane < K_NB) ? yd_s[lane * 4 + h] : -1e30f;
        float l2 = (lane < K_NB - 32) ? yd_s[(lane + 32) * 4 + h] : -1e30f;
        float m = fmaxf(l1, l2);
        #pragma unroll
        for (int o = 16; o; o >>= 1) m = fmaxf(m, __shfl_xor_sync(0xffffffffu, m, o));
        float e1 = (lane < K_NB) ? expf(l1 - m) : 0.f;
        float e2 = (lane < K_NB - 32) ? expf(l2 - m) : 0.f;
        float se = e1 + e2;
        #pragma unroll
        for (int o = 16; o; o >>= 1) se += __shfl_xor_sync(0xffffffffu, se, o);
        float invs = 1.0f / se;
        float wv1 = 0.f, wv2 = 0.f;
        if (lane < K_NB)      { wv1 = e1 * invs * rs_s[lane];      w_s[h][lane]      = wv1; }
        if (lane < K_NB - 32) { wv2 = e2 * invs * rs_s[lane + 32]; w_s[h][lane + 32] = wv2; }
        float cp = (lane < K_NB ? wv1 * mu_s[lane] : 0.f) +
                   (lane < K_NB - 32 ? wv2 * mu_s[lane + 32] : 0.f);
        #pragma unroll
        for (int o = 16; o; o >>= 1) cp += __shfl_xor_sync(0xffffffffu, cp, o);
        if (lane == 0) csub[h] = cp;
    }
    __syncthreads();

    // ---- phase 3: weighted sum (threads 0..191), y[n] should be L2-hot ----
    if (tid < E4) {
        float4 acc[H_NUM];
        #pragma unroll
        for (int h = 0; h < H_NUM; h++) { acc[h].x = 0.f; acc[h].y = 0.f; acc[h].z = 0.f; acc[h].w = 0.f; }
        #pragma unroll 4
        for (int k = 0; k < K_NB; k++) {
            float4 v = yb[k * E4 + tid];
            #pragma unroll
            for (int h = 0; h < H_NUM; h++) {
                float wv = w_s[h][k];
                acc[h].x += wv * v.x; acc[h].y += wv * v.y;
                acc[h].z += wv * v.z; acc[h].w += wv * v.w;
            }
        }
        #pragma unroll
        for (int h = 0; h < H_NUM; h++) {
            float4 ga = ((const float4*)gamma)[h * E4 + tid];
            float4 be = ((const float4*)beta)[h * E4 + tid];
            float c = csub[h];
            float o0 = (acc[h].x - c) * ga.x + be.x;
            float o1 = (acc[h].y - c) * ga.y + be.y;
            float o2 = (acc[h].z - c) * ga.z + be.z;
            float o3 = (acc[h].w - c) * ga.w + be.w;
            long base = ((long)h * BS_TOT + n) * E_DIM + tid * 4;
            __nv_bfloat16 h0, h1, h2, h3, l0, l1, l2, l3;
            bf16_split(o0, h0, l0); bf16_split(o1, h1, l1);
            bf16_split(o2, h2, l2); bf16_split(o3, h3, l3);
            __nv_bfloat162* ph = (__nv_bfloat162*)(g_a_hi + base);
            __nv_bfloat162* pl = (__nv_bfloat162*)(g_a_lo + base);
            ph[0] = __halves2bfloat162(h0, h1); ph[1] = __halves2bfloat162(h2, h3);
            pl[0] = __halves2bfloat162(l0, l1); pl[1] = __halves2bfloat162(l2, l3);
        }
    }
}

// ================= HMMA (mma.sync bf16) split GEMM =================
#define TM 128
#define TN 128
#define KC 32
#define ROWB   80
#define BUF_SZ (128 * ROWB)
#define SA_HI  0
#define SA_LO  (BUF_SZ)
#define SB_HI  (2 * BUF_SZ)
#define SB_LO  (3 * BUF_SZ)
#define STAGE  (4 * BUF_SZ)
#define GEMM_SMEM (2 * STAGE)

template <int MODE>
__global__ __launch_bounds__(256) void gemm_mma(
    const __nv_bfloat16* __restrict__ Ahi, const __nv_bfloat16* __restrict__ Alo,
    long aBatch, int lda,
    const __nv_bfloat16* __restrict__ Bhi, const __nv_bfloat16* __restrict__ Blo,
    long bBatch, int ldb,
    const float* __restrict__ bias, int biasBatch,
    const float* __restrict__ x,
    float* __restrict__ outF,
    __nv_bfloat16* __restrict__ outHi, __nv_bfloat16* __restrict__ outLo,
    int ldc, int colBatch, int K) {
    extern __shared__ char smem[];
    uint32_t sb = smem_u32(smem);
    const int tid = threadIdx.x, w = tid >> 5, l = tid & 31;

    int z = blockIdx.z;
    Ahi += (long)z * aBatch; Alo += (long)z * aBatch;
    Bhi += (long)z * bBatch; Blo += (long)z * bBatch;
    bias += (long)z * biasBatch;
    const int coloff = z * colBatch;
    const int m0 = blockIdx.y * TM, n0 = blockIdx.x * TN;
    const int wm = (w >> 2) * 64, wn = (w & 3) * 32;

    const int gr = tid >> 2, gc = tid & 3;
    const long aoff0 = ((long)(m0 + gr) * lda + gc * 8) * 2;
    const long aoff1 = aoff0 + (long)64 * lda * 2;
    const long boff0 = ((long)(n0 + gr) * ldb + gc * 8) * 2;
    const long boff1 = boff0 + (long)64 * ldb * 2;
    const uint32_t soff0 = gr * ROWB + gc * 16;
    const uint32_t soff1 = (gr + 64) * ROWB + gc * 16;
    const char* aH = (const char*)Ahi;
    const char* aL = (const char*)Alo;
    const char* bH = (const char*)Bhi;
    const char* bL = (const char*)Blo;

    const uint32_t a_r = (l & 15) * ROWB + (l >> 4) * 16;
    const uint32_t b_r = (((l >> 4) & 1) * 8 + (l & 7)) * ROWB + ((l >> 3) & 1) * 16;

    float acc[4][4][4];
    #pragma unroll
    for (int i = 0; i < 4; i++)
        #pragma unroll
        for (int j = 0; j < 4; j++)
            #pragma unroll
            for (int q = 0; q < 4; q++) acc[i][j][q] = 0.f;

    const int NC = K / KC;

    {
        uint32_t s0 = sb;
        CP_ASYNC16(s0 + SA_HI + soff0, aH + aoff0);
        CP_ASYNC16(s0 + SA_HI + soff1, aH + aoff1);
        CP_ASYNC16(s0 + SA_LO + soff0, aL + aoff0);
        CP_ASYNC16(s0 + SA_LO + soff1, aL + aoff1);
        CP_ASYNC16(s0 + SB_HI + soff0, bH + boff0);
        CP_ASYNC16(s0 + SB_HI + soff1, bH + boff1);
        CP_ASYNC16(s0 + SB_LO + soff0, bL + boff0);
        CP_ASYNC16(s0 + SB_LO + soff1, bL + boff1);
        CP_COMMIT();
    }

    for (int c = 0; c < NC; c++) {
        if (c + 1 < NC) {
            uint32_t sn = sb + ((c + 1) & 1) * STAGE;
            long kb = (long)(c + 1) * KC * 2;
            CP_ASYNC16(sn + SA_HI + soff0, aH + aoff0 + kb);
            CP_ASYNC16(sn + SA_HI + soff1, aH + aoff1 + kb);
            CP_ASYNC16(sn + SA_LO + soff0, aL + aoff0 + kb);
            CP_ASYNC16(sn + SA_LO + soff1, aL + aoff1 + kb);
            CP_ASYNC16(sn + SB_HI + soff0, bH + boff0 + kb);
            CP_ASYNC16(sn + SB_HI + soff1, bH + boff1 + kb);
            CP_ASYNC16(sn + SB_LO + soff0, bL + boff0 + kb);
            CP_ASYNC16(sn + SB_LO + soff1, bL + boff1 + kb);
            CP_COMMIT();
            CP_WAIT(1);
        } else {
            CP_WAIT(0);
        }
        __syncthreads();

        uint32_t st = sb + (c & 1) * STAGE;
        #pragma unroll
        for (int kk = 0; kk < 2; kk++) {
            uint32_t kby = kk * 32;
            uint32_t ah[4][4], al[4][4], bh[2][4], bl[2][4];
            #pragma unroll
            for (int mt = 0; mt < 4; mt++) {
                uint32_t ra = st + SA_HI + (wm + mt * 16) * ROWB + a_r + kby;
                LDSM_X4(ah[mt][0], ah[mt][1], ah[mt][2], ah[mt][3], ra);
                uint32_t rl = st + SA_LO + (wm + mt * 16) * ROWB + a_r + kby;
                LDSM_X4(al[mt][0], al[mt][1], al[mt][2], al[mt][3], rl);
            }
            #pragma unroll
            for (int np = 0; np < 2; np++) {
                uint32_t rb = st + SB_HI + (wn + np * 16) * ROWB + b_r + kby;
                LDSM_X4(bh[np][0], bh[np][1], bh[np][2], bh[np][3], rb);
                uint32_t rc = st + SB_LO + (wn + np * 16) * ROWB + b_r + kby;
                LDSM_X4(bl[np][0], bl[np][1], bl[np][2], bl[np][3], rc);
            }
            #pragma unroll
            for (int mt = 0; mt < 4; mt++) {
                #pragma unroll
                for (int nt = 0; nt < 4; nt++) {
                    uint32_t bh0 = bh[nt >> 1][(nt & 1) * 2];
                    uint32_t bh1 = bh[nt >> 1][(nt & 1) * 2 + 1];
                    uint32_t bl0 = bl[nt >> 1][(nt & 1) * 2];
                    uint32_t bl1 = bl[nt >> 1][(nt & 1) * 2 + 1];
                    MMA16816(acc[mt][nt], ah[mt], bh0, bh1);
                    MMA16816(acc[mt][nt], ah[mt], bl0, bl1);
                    MMA16816(acc[mt][nt], al[mt], bh0, bh1);
                }
            }
        }
        __syncthreads();
    }

    #pragma unroll
    for (int mt = 0; mt < 4; mt++) {
        #pragma unroll
        for (int nt = 0; nt < 4; nt++) {
            int row0 = m0 + wm + mt * 16 + (l >> 2);
            int col = n0 + wn + nt * 8 + ((l & 3) << 1);
            #pragma unroll
            for (int rh = 0; rh < 2; rh++) {
                int row = row0 + rh * 8;
                float d0 = acc[mt][nt][rh * 2 + 0];
                float d1 = acc[mt][nt][rh * 2 + 1];
                float2 xv = *(const float2*)(x + (long)row * E_DIM + col);
                float2 bv = *(const float2*)(bias + col);
                if (MODE == 0) {
                    float o0 = gelu_tanh(xv.x + d0 + bv.x);
                    float o1 = gelu_tanh(xv.y + d1 + bv.y);
                    __nv_bfloat16 h0, h1, l0v, l1v;
                    bf16_split(o0, h0, l0v);
                    bf16_split(o1, h1, l1v);
                    long cb = (long)row * ldc + coloff + col;
                    *(__nv_bfloat162*)(outHi + cb) = __halves2bfloat162(h0, h1);
                    *(__nv_bfloat162*)(outLo + cb) = __halves2bfloat162(l0v, l1v);
                } else {
                    float2 o;
                    o.x = xv.x + gelu_tanh(d0 + bv.x);
                    o.y = xv.y + gelu_tanh(d1 + bv.y);
                    *(float2*)(outF + (long)row * ldc + col) = o;
                }
            }
        }
    }
}

// ---------------- launch ----------------
extern "C" void kernel_launch(void* const* d_in, const int* in_sizes, int n_in,
                              void* d_out, int out_size) {
    (void)in_sizes; (void)n_in; (void)out_size;
    const float* x     = (const float*)d_in[0];   // [2048,768]
    const float* y     = (const float*)d_in[1];   // [2048,36,768]
    const float* gamma = (const float*)d_in[2];   // [4,768]
    const float* beta  = (const float*)d_in[3];   // [4,768]
    const float* W1    = (const float*)d_in[4];   // [4,768,768]
    const float* b1    = (const float*)d_in[5];   // [4,768]
    // d_in[6] = W2x, d_in[8] = b2: cancel in the softmax — unused.
    const float* W2y   = (const float*)d_in[7];   // [4,768]
    const float* Wm    = (const float*)d_in[9];   // [3072,768]
    const float* bm    = (const float*)d_in[10];  // [768]
    float* out = (float*)d_out;

    __nv_bfloat16 *p_a_hi, *p_a_lo, *p_w1t_hi, *p_w1t_lo, *p_cat_hi, *p_cat_lo, *p_wmt_hi, *p_wmt_lo;
    cudaGetSymbolAddress((void**)&p_a_hi, g_a_hi);
    cudaGetSymbolAddress((void**)&p_a_lo, g_a_lo);
    cudaGetSymbolAddress((void**)&p_w1t_hi, g_w1t_hi);
    cudaGetSymbolAddress((void**)&p_w1t_lo, g_w1t_lo);
    cudaGetSymbolAddress((void**)&p_cat_hi, g_cat_hi);
    cudaGetSymbolAddress((void**)&p_cat_lo, g_cat_lo);
    cudaGetSymbolAddress((void**)&p_wmt_hi, g_wmt_hi);
    cudaGetSymbolAddress((void**)&p_wmt_lo, g_wmt_lo);

    cudaFuncSetAttribute(gemm_mma<0>, cudaFuncAttributeMaxDynamicSharedMemorySize, GEMM_SMEM);
    cudaFuncSetAttribute(gemm_mma<1>, cudaFuncAttributeMaxDynamicSharedMemorySize, GEMM_SMEM);

    prep_u<<<384, 256>>>(W1, W2y, gamma);
    transpose_split<<<dim3(24, 24, 4), dim3(32, 8)>>>(W1, 768, 768, 768L * 768,
                                                      p_w1t_hi, p_w1t_lo, 768L * 768);
    transpose_split<<<dim3(96, 24, 1), dim3(32, 8)>>>(Wm, 3072, 768, 0,
                                                      p_wmt_hi, p_wmt_lo, 0);
    fused_y<<<BS_TOT, 256>>>(y, gamma, beta);

    // GEMM1 (per head): cat[:, h*768+n] = GELU(x + A_h @ W1[h]^T + b1[h])
    gemm_mma<0><<<dim3(E_DIM / TN, BS_TOT / TM, H_NUM), 256, GEMM_SMEM>>>(
        p_a_hi, p_a_lo, (long)BS_TOT * E_DIM, E_DIM,
        p_w1t_hi, p_w1t_lo, (long)E_DIM * E_DIM, E_DIM,
        b1, E_DIM, x,
        nullptr, p_cat_hi, p_cat_lo, CATD, E_DIM, E_DIM);
    // GEMM2: out = x + GELU(cat @ WmT^T + bm)
    gemm_mma<1><<<dim3(E_DIM / TN, BS_TOT / TM, 1), 256, GEMM_SMEM>>>(
        p_cat_hi, p_cat_lo, 0, CATD,
        p_wmt_hi, p_wmt_lo, 0, CATD,
        bm, 0, x,
        out, nullptr, nullptr, E_DIM, 0, CATD);
}

// round 5
// speedup vs baseline: 2.1472x; 1.0392x over previous
#include <cuda_runtime.h>
#include <cuda_fp16.h>
#include <cstdint>

// Problem constants (fixed by setup_inputs)
#define BS_TOT 2048      // B*S
#define E_DIM  768
#define E4     192       // E/4
#define K_NB   36
#define H_NUM  4
#define CATD   (H_NUM * E_DIM)   // 3072

// ---------------- scratch (device globals; no allocations) ----------------
__device__ float g_u[H_NUM * E_DIM];                    // gamma ⊙ (W1 @ W2y)

// fp16 buffers for HMMA GEMMs
__device__ __half g_a[(long)H_NUM * BS_TOT * E_DIM];     // attention out per head
__device__ __half g_w1t[(long)H_NUM * E_DIM * E_DIM];    // W1^T per head
__device__ __half g_cat[(long)BS_TOT * CATD];            // concat head outputs
__device__ __half g_wmt[(long)E_DIM * CATD];             // Wm^T

__device__ __forceinline__ float gelu_tanh(float v) {
    const float c = 0.7978845608028654f;   // sqrt(2/pi)
    float t = tanhf(c * (v + 0.044715f * v * v * v));
    return 0.5f * v * (1.0f + t);
}

__device__ __forceinline__ uint32_t smem_u32(const void* p) {
    uint32_t a;
    asm("{ .reg .u64 t; cvta.to.shared.u64 t, %1; cvt.u32.u64 %0, t; }" : "=r"(a) : "l"(p));
    return a;
}

#define CP_ASYNC16(sm, gm) \
    asm volatile("cp.async.cg.shared.global [%0], [%1], 16;" :: "r"(sm), "l"(gm))
#define CP_COMMIT() asm volatile("cp.async.commit_group;" ::: "memory")
#define CP_WAIT(n)  asm volatile("cp.async.wait_group %0;" :: "n"(n) : "memory")

#define LDSM_X4(r0, r1, r2, r3, a) \
    asm volatile("ldmatrix.sync.aligned.m8n8.x4.shared.b16 {%0,%1,%2,%3}, [%4];" \
                 : "=r"(r0), "=r"(r1), "=r"(r2), "=r"(r3) : "r"(a))

#define MMA16816(d, a, b0v, b1v) \
    asm volatile("mma.sync.aligned.m16n8k16.row.col.f32.f16.f16.f32 " \
                 "{%0,%1,%2,%3}, {%4,%5,%6,%7}, {%8,%9}, {%0,%1,%2,%3};" \
                 : "+f"((d)[0]), "+f"((d)[1]), "+f"((d)[2]), "+f"((d)[3]) \
                 : "r"((a)[0]), "r"((a)[1]), "r"((a)[2]), "r"((a)[3]), \
                   "r"(b0v), "r"(b1v))

// ---------------- kernel P: u[h][i] = gamma[h][i] * sum_j W1[h][i][j]*W2y[h][j]
__global__ void prep_u(const float* __restrict__ W1,
                       const float* __restrict__ W2y,
                       const float* __restrict__ gamma) {
    int warp = (blockIdx.x * blockDim.x + threadIdx.x) >> 5;
    int lane = threadIdx.x & 31;
    if (warp >= H_NUM * E_DIM) return;
    int h = warp / E_DIM;
    const float* wrow = W1 + (long)warp * E_DIM;
    const float* w2 = W2y + h * E_DIM;
    float s = 0.f;
    #pragma unroll 4
    for (int j = lane; j < E_DIM; j += 32) s += wrow[j] * w2[j];
    #pragma unroll
    for (int o = 16; o; o >>= 1) s += __shfl_xor_sync(0xffffffffu, s, o);
    if (lane == 0) g_u[warp] = gamma[warp] * s;
}

// ---------------- transpose + fp16 convert: out[n][k] = half(in[k][n])
__global__ void transpose_h(const float* __restrict__ in, int K, int N, long inBatch,
                            __half* __restrict__ oh, long outBatch) {
    __shared__ float t[32][33];
    int z = blockIdx.z;
    in += (long)z * inBatch;
    oh += (long)z * outBatch;
    int k0 = blockIdx.x * 32, n0 = blockIdx.y * 32;
    for (int i = threadIdx.y; i < 32; i += 8)
        t[i][threadIdx.x] = in[(long)(k0 + i) * N + n0 + threadIdx.x];
    __syncthreads();
    for (int i = threadIdx.y; i < 32; i += 8) {
        float v = t[threadIdx.x][i];
        oh[(long)(n0 + i) * K + k0 + threadIdx.x] = __float2half(v);
    }
}

// ---------------- fused y kernel: one CTA per token n (192 threads) ----------------
// Phase 1: per-row (k) LN stats + dots with u[h]  (reads y[n], DRAM)
// Phase 2: softmax over k per head (pure smem)
// Phase 3: weighted sum over k (re-reads y[n], L2-hot) -> fp16 A
__global__ __launch_bounds__(192, 5) void fused_y(const float* __restrict__ y,
                                                  const float* __restrict__ gamma,
                                                  const float* __restrict__ beta) {
    __shared__ float4 u_s[H_NUM * E4];     // 12 KB
    __shared__ float yd_s[K_NB * 4];       // dots*rstd, [k][h]
    __shared__ float mu_s[K_NB];
    __shared__ float rs_s[K_NB];
    __shared__ float w_s[H_NUM][K_NB];     // prob * rstd
    __shared__ float csub[H_NUM];

    const int n = blockIdx.x;
    const int tid = threadIdx.x;
    const int w = tid >> 5, lane = tid & 31;

    const float4* u4 = (const float4*)g_u;
    for (int i = tid; i < H_NUM * E4; i += 192) u_s[i] = u4[i];
    __syncthreads();

    const float4* yb = (const float4*)y + (long)n * K_NB * E4;

    // ---- phase 1: 6 warps, rows k = w, w+6, ... ----
    for (int k = w; k < K_NB; k += 6) {
        const float4* yr = yb + (long)k * E4;
        float4 v[6];
        float s = 0.f, sq = 0.f;
        #pragma unroll
        for (int j = 0; j < 6; j++) {
            v[j] = yr[lane + 32 * j];
            s  += v[j].x + v[j].y + v[j].z + v[j].w;
            sq += v[j].x * v[j].x + v[j].y * v[j].y + v[j].z * v[j].z + v[j].w * v[j].w;
        }
        #pragma unroll
        for (int o = 16; o; o >>= 1) {
            s  += __shfl_xor_sync(0xffffffffu, s, o);
            sq += __shfl_xor_sync(0xffffffffu, sq, o);
        }
        const float inv = 1.0f / 768.0f;
        float mean = s * inv;
        float var  = sq * inv - mean * mean;
        float rstd = rsqrtf(var + 1e-5f);

        float p0 = 0.f, p1 = 0.f, p2 = 0.f, p3 = 0.f;
        #pragma unroll
        for (int j = 0; j < 6; j++) {
            int idx = lane + 32 * j;
            float tx = v[j].x - mean, ty = v[j].y - mean, tz = v[j].z - mean, tw = v[j].w - mean;
            float4 u0 = u_s[idx];
            float4 u1 = u_s[E4 + idx];
            float4 u2 = u_s[2 * E4 + idx];
            float4 u3 = u_s[3 * E4 + idx];
            p0 += tx * u0.x + ty * u0.y + tz * u0.z + tw * u0.w;
            p1 += tx * u1.x + ty * u1.y + tz * u1.z + tw * u1.w;
            p2 += tx * u2.x + ty * u2.y + tz * u2.z + tw * u2.w;
            p3 += tx * u3.x + ty * u3.y + tz * u3.z + tw * u3.w;
        }
        #pragma unroll
        for (int o = 16; o; o >>= 1) {
            p0 += __shfl_xor_sync(0xffffffffu, p0, o);
            p1 += __shfl_xor_sync(0xffffffffu, p1, o);
            p2 += __shfl_xor_sync(0xffffffffu, p2, o);
            p3 += __shfl_xor_sync(0xffffffffu, p3, o);
        }
        if (lane == 0) {
            mu_s[k] = mean;
            rs_s[k] = rstd;
            yd_s[k * 4 + 0] = p0 * rstd;
            yd_s[k * 4 + 1] = p1 * rstd;
            yd_s[k * 4 + 2] = p2 * rstd;
            yd_s[k * 4 + 3] = p3 * rstd;
        }
    }
    __syncthreads();

    // ---- phase 2: softmax per head (warps 0..3) ----
    if (w < H_NUM) {
        int h = w;
        float l1 = (lane < K_NB) ? yd_s[lane * 4 + h] : -1e30f;
        float l2 = (lane < K_NB - 32) ? yd_s[(lane + 32) * 4 + h] : -1e30f;
        float m = fmaxf(l1, l2);
        #pragma unroll
        for (int o = 16; o; o >>= 1) m = fmaxf(m, __shfl_xor_sync(0xffffffffu, m, o));
        float e1 = (lane < K_NB) ? expf(l1 - m) : 0.f;
        float e2 = (lane < K_NB - 32) ? expf(l2 - m) : 0.f;
        float se = e1 + e2;
        #pragma unroll
        for (int o = 16; o; o >>= 1) se += __shfl_xor_sync(0xffffffffu, se, o);
        float invs = 1.0f / se;
        float wv1 = 0.f, wv2 = 0.f;
        if (lane < K_NB)      { wv1 = e1 * invs * rs_s[lane];      w_s[h][lane]      = wv1; }
        if (lane < K_NB - 32) { wv2 = e2 * invs * rs_s[lane + 32]; w_s[h][lane + 32] = wv2; }
        float cp = (lane < K_NB ? wv1 * mu_s[lane] : 0.f) +
                   (lane < K_NB - 32 ? wv2 * mu_s[lane + 32] : 0.f);
        #pragma unroll
        for (int o = 16; o; o >>= 1) cp += __shfl_xor_sync(0xffffffffu, cp, o);
        if (lane == 0) csub[h] = cp;
    }
    __syncthreads();

    // ---- phase 3: weighted sum, all 192 threads (one float4 col each) ----
    {
        float4 acc[H_NUM];
        #pragma unroll
        for (int h = 0; h < H_NUM; h++) { acc[h].x = 0.f; acc[h].y = 0.f; acc[h].z = 0.f; acc[h].w = 0.f; }
        #pragma unroll 4
        for (int k = 0; k < K_NB; k++) {
            float4 v = yb[k * E4 + tid];
            #pragma unroll
            for (int h = 0; h < H_NUM; h++) {
                float wv = w_s[h][k];
                acc[h].x += wv * v.x; acc[h].y += wv * v.y;
                acc[h].z += wv * v.z; acc[h].w += wv * v.w;
            }
        }
        #pragma unroll
        for (int h = 0; h < H_NUM; h++) {
            float4 ga = ((const float4*)gamma)[h * E4 + tid];
            float4 be = ((const float4*)beta)[h * E4 + tid];
            float c = csub[h];
            float o0 = (acc[h].x - c) * ga.x + be.x;
            float o1 = (acc[h].y - c) * ga.y + be.y;
            float o2 = (acc[h].z - c) * ga.z + be.z;
            float o3 = (acc[h].w - c) * ga.w + be.w;
            long base = ((long)h * BS_TOT + n) * E_DIM + tid * 4;
            __half2* pa = (__half2*)(g_a + base);
            pa[0] = __floats2half2_rn(o0, o1);
            pa[1] = __floats2half2_rn(o2, o3);
        }
    }
}

// ================= HMMA (mma.sync fp16) GEMM =================
// D[m][n] = sum_k A[m][k]*B[n][k], fp16 operands, fp32 accumulate.
// MODE 0: cat[m][coloff+n] = half(GELU(x[m][n] + D + bias[n]))
// MODE 1: outF[m][n] = x[m][n] + GELU(D + bias[n])
#define TM 128
#define TN 128
#define KC 32
#define ROWB   80                     // 32 halfs (64B) + 16B pad: conflict-free LDSM
#define BUF_SZ (128 * ROWB)           // 10240 B
#define S_A    0
#define S_B    (BUF_SZ)
#define STAGE  (2 * BUF_SZ)           // 20480 B
#define GEMM_SMEM (2 * STAGE)         // 40960 B

template <int MODE>
__global__ __launch_bounds__(256) void gemm_mma(
    const __half* __restrict__ A, long aBatch, int lda,
    const __half* __restrict__ B, long bBatch, int ldb,
    const float* __restrict__ bias, int biasBatch,
    const float* __restrict__ x,
    float* __restrict__ outF, __half* __restrict__ outC,
    int ldc, int colBatch, int K) {
    extern __shared__ char smem[];
    uint32_t sb = smem_u32(smem);
    const int tid = threadIdx.x, w = tid >> 5, l = tid & 31;

    int z = blockIdx.z;
    A += (long)z * aBatch;
    B += (long)z * bBatch;
    bias += (long)z * biasBatch;
    const int coloff = z * colBatch;
    const int m0 = blockIdx.y * TM, n0 = blockIdx.x * TN;
    const int wm = (w >> 2) * 64, wn = (w & 3) * 32;

    // gmem->smem: thread handles rows (tid>>2), (tid>>2)+64; 16B chunk (tid&3)
    const int gr = tid >> 2, gc = tid & 3;
    const long aoff0 = ((long)(m0 + gr) * lda + gc * 8) * 2;
    const long aoff1 = aoff0 + (long)64 * lda * 2;
    const long boff0 = ((long)(n0 + gr) * ldb + gc * 8) * 2;
    const long boff1 = boff0 + (long)64 * ldb * 2;
    const uint32_t soff0 = gr * ROWB + gc * 16;
    const uint32_t soff1 = (gr + 64) * ROWB + gc * 16;
    const char* aB = (const char*)A;
    const char* bB = (const char*)B;

    const uint32_t a_r = (l & 15) * ROWB + (l >> 4) * 16;
    const uint32_t b_r = (((l >> 4) & 1) * 8 + (l & 7)) * ROWB + ((l >> 3) & 1) * 16;

    float acc[4][4][4];
    #pragma unroll
    for (int i = 0; i < 4; i++)
        #pragma unroll
        for (int j = 0; j < 4; j++)
            #pragma unroll
            for (int q = 0; q < 4; q++) acc[i][j][q] = 0.f;

    const int NC = K / KC;

    {
        CP_ASYNC16(sb + S_A + soff0, aB + aoff0);
        CP_ASYNC16(sb + S_A + soff1, aB + aoff1);
        CP_ASYNC16(sb + S_B + soff0, bB + boff0);
        CP_ASYNC16(sb + S_B + soff1, bB + boff1);
        CP_COMMIT();
    }

    for (int c = 0; c < NC; c++) {
        if (c + 1 < NC) {
            uint32_t sn = sb + ((c + 1) & 1) * STAGE;
            long kb = (long)(c + 1) * KC * 2;
            CP_ASYNC16(sn + S_A + soff0, aB + aoff0 + kb);
            CP_ASYNC16(sn + S_A + soff1, aB + aoff1 + kb);
            CP_ASYNC16(sn + S_B + soff0, bB + boff0 + kb);
            CP_ASYNC16(sn + S_B + soff1, bB + boff1 + kb);
            CP_COMMIT();
            CP_WAIT(1);
        } else {
            CP_WAIT(0);
        }
        __syncthreads();

        uint32_t st = sb + (c & 1) * STAGE;
        #pragma unroll
        for (int kk = 0; kk < 2; kk++) {
            uint32_t kby = kk * 32;   // 16 halfs = 32B
            uint32_t ah[4][4], bh[2][4];
            #pragma unroll
            for (int mt = 0; mt < 4; mt++) {
                uint32_t ra = st + S_A + (wm + mt * 16) * ROWB + a_r + kby;
                LDSM_X4(ah[mt][0], ah[mt][1], ah[mt][2], ah[mt][3], ra);
            }
            #pragma unroll
            for (int np = 0; np < 2; np++) {
                uint32_t rb = st + S_B + (wn + np * 16) * ROWB + b_r + kby;
                LDSM_X4(bh[np][0], bh[np][1], bh[np][2], bh[np][3], rb);
            }
            #pragma unroll
            for (int mt = 0; mt < 4; mt++) {
                #pragma unroll
                for (int nt = 0; nt < 4; nt++) {
                    MMA16816(acc[mt][nt], ah[mt],
                             bh[nt >> 1][(nt & 1) * 2], bh[nt >> 1][(nt & 1) * 2 + 1]);
                }
            }
        }
        __syncthreads();
    }

    // epilogue
    #pragma unroll
    for (int mt = 0; mt < 4; mt++) {
        #pragma unroll
        for (int nt = 0; nt < 4; nt++) {
            int row0 = m0 + wm + mt * 16 + (l >> 2);
            int col = n0 + wn + nt * 8 + ((l & 3) << 1);
            #pragma unroll
            for (int rh = 0; rh < 2; rh++) {
                int row = row0 + rh * 8;
                float d0 = acc[mt][nt][rh * 2 + 0];
                float d1 = acc[mt][nt][rh * 2 + 1];
                float2 xv = *(const float2*)(x + (long)row * E_DIM + col);
                float2 bv = *(const float2*)(bias + col);
                if (MODE == 0) {
                    float o0 = gelu_tanh(xv.x + d0 + bv.x);
                    float o1 = gelu_tanh(xv.y + d1 + bv.y);
                    *(__half2*)(outC + (long)row * ldc + coloff + col) =
                        __floats2half2_rn(o0, o1);
                } else {
                    float2 o;
                    o.x = xv.x + gelu_tanh(d0 + bv.x);
                    o.y = xv.y + gelu_tanh(d1 + bv.y);
                    *(float2*)(outF + (long)row * ldc + col) = o;
                }
            }
        }
    }
}

// ---------------- launch ----------------
extern "C" void kernel_launch(void* const* d_in, const int* in_sizes, int n_in,
                              void* d_out, int out_size) {
    (void)in_sizes; (void)n_in; (void)out_size;
    const float* x     = (const float*)d_in[0];   // [2048,768]
    const float* y     = (const float*)d_in[1];   // [2048,36,768]
    const float* gamma = (const float*)d_in[2];   // [4,768]
    const float* beta  = (const float*)d_in[3];   // [4,768]
    const float* W1    = (const float*)d_in[4];   // [4,768,768]
    const float* b1    = (const float*)d_in[5];   // [4,768]
    // d_in[6] = W2x, d_in[8] = b2: cancel in the softmax — unused.
    const float* W2y   = (const float*)d_in[7];   // [4,768]
    const float* Wm    = (const float*)d_in[9];   // [3072,768]
    const float* bm    = (const float*)d_in[10];  // [768]
    float* out = (float*)d_out;

    __half *p_a, *p_w1t, *p_cat, *p_wmt;
    cudaGetSymbolAddress((void**)&p_a, g_a);
    cudaGetSymbolAddress((void**)&p_w1t, g_w1t);
    cudaGetSymbolAddress((void**)&p_cat, g_cat);
    cudaGetSymbolAddress((void**)&p_wmt, g_wmt);

    cudaFuncSetAttribute(gemm_mma<0>, cudaFuncAttributeMaxDynamicSharedMemorySize, GEMM_SMEM);
    cudaFuncSetAttribute(gemm_mma<1>, cudaFuncAttributeMaxDynamicSharedMemorySize, GEMM_SMEM);

    prep_u<<<384, 256>>>(W1, W2y, gamma);
    transpose_h<<<dim3(24, 24, 4), dim3(32, 8)>>>(W1, 768, 768, 768L * 768,
                                                  p_w1t, 768L * 768);
    transpose_h<<<dim3(96, 24, 1), dim3(32, 8)>>>(Wm, 3072, 768, 0, p_wmt, 0);
    fused_y<<<BS_TOT, 192>>>(y, gamma, beta);

    // GEMM1 (per head): cat[:, h*768+n] = GELU(x + A_h @ W1[h]^T + b1[h])
    gemm_mma<0><<<dim3(E_DIM / TN, BS_TOT / TM, H_NUM), 256, GEMM_SMEM>>>(
        p_a, (long)BS_TOT * E_DIM, E_DIM,
        p_w1t, (long)E_DIM * E_DIM, E_DIM,
        b1, E_DIM, x,
        nullptr, p_cat, CATD, E_DIM, E_DIM);
    // GEMM2: out = x + GELU(cat @ WmT^T + bm)
    gemm_mma<1><<<dim3(E_DIM / TN, BS_TOT / TM, 1), 256, GEMM_SMEM>>>(
        p_cat, 0, CATD,
        p_wmt, 0, CATD,
        bm, 0, x,
        out, nullptr, E_DIM, 0, CATD);
}

// round 6
// speedup vs baseline: 3.2094x; 1.4947x over previous
#include <cuda_runtime.h>
#include <cuda_fp16.h>
#include <cstdint>

// Problem constants (fixed by setup_inputs)
#define BS_TOT 2048      // B*S
#define E_DIM  768
#define E4     192       // E/4
#define K_NB   36
#define H_NUM  4
#define CATD   (H_NUM * E_DIM)   // 3072

// ---------------- scratch (device globals; no allocations) ----------------
__device__ float g_u[H_NUM * E_DIM];                    // gamma ⊙ (W1 @ W2y)

// fp16 buffers for HMMA GEMMs
__device__ __half g_a[(long)H_NUM * BS_TOT * E_DIM];     // attention out per head
__device__ __half g_w1t[(long)H_NUM * E_DIM * E_DIM];    // W1^T per head
__device__ __half g_cat[(long)BS_TOT * CATD];            // concat head outputs
__device__ __half g_wmt[(long)E_DIM * CATD];             // Wm^T

__device__ __forceinline__ float gelu_tanh(float v) {
    const float c = 0.7978845608028654f;   // sqrt(2/pi)
    float t = tanhf(c * (v + 0.044715f * v * v * v));
    return 0.5f * v * (1.0f + t);
}

__device__ __forceinline__ uint32_t smem_u32(const void* p) {
    uint32_t a;
    asm("{ .reg .u64 t; cvta.to.shared.u64 t, %1; cvt.u32.u64 %0, t; }" : "=r"(a) : "l"(p));
    return a;
}

#define CP_ASYNC16(sm, gm) \
    asm volatile("cp.async.cg.shared.global [%0], [%1], 16;" :: "r"(sm), "l"(gm))
#define CP_COMMIT() asm volatile("cp.async.commit_group;" ::: "memory")
#define CP_WAIT(n)  asm volatile("cp.async.wait_group %0;" :: "n"(n) : "memory")

#define LDSM_X4(r0, r1, r2, r3, a) \
    asm volatile("ldmatrix.sync.aligned.m8n8.x4.shared.b16 {%0,%1,%2,%3}, [%4];" \
                 : "=r"(r0), "=r"(r1), "=r"(r2), "=r"(r3) : "r"(a))

#define MMA16816(d, a, b0v, b1v) \
    asm volatile("mma.sync.aligned.m16n8k16.row.col.f32.f16.f16.f32 " \
                 "{%0,%1,%2,%3}, {%4,%5,%6,%7}, {%8,%9}, {%0,%1,%2,%3};" \
                 : "+f"((d)[0]), "+f"((d)[1]), "+f"((d)[2]), "+f"((d)[3]) \
                 : "r"((a)[0]), "r"((a)[1]), "r"((a)[2]), "r"((a)[3]), \
                   "r"(b0v), "r"(b1v))

// ---------------- kernel P: u[h][i] = gamma[h][i] * sum_j W1[h][i][j]*W2y[h][j]
__global__ void prep_u(const float* __restrict__ W1,
                       const float* __restrict__ W2y,
                       const float* __restrict__ gamma) {
    int warp = (blockIdx.x * blockDim.x + threadIdx.x) >> 5;
    int lane = threadIdx.x & 31;
    if (warp >= H_NUM * E_DIM) return;
    int h = warp / E_DIM;
    const float* wrow = W1 + (long)warp * E_DIM;
    const float* w2 = W2y + h * E_DIM;
    float s = 0.f;
    #pragma unroll 4
    for (int j = lane; j < E_DIM; j += 32) s += wrow[j] * w2[j];
    #pragma unroll
    for (int o = 16; o; o >>= 1) s += __shfl_xor_sync(0xffffffffu, s, o);
    if (lane == 0) g_u[warp] = gamma[warp] * s;
}

// ---------------- transpose + fp16 convert: out[n][k] = half(in[k][n])
__global__ void transpose_h(const float* __restrict__ in, int K, int N, long inBatch,
                            __half* __restrict__ oh, long outBatch) {
    __shared__ float t[32][33];
    int z = blockIdx.z;
    in += (long)z * inBatch;
    oh += (long)z * outBatch;
    int k0 = blockIdx.x * 32, n0 = blockIdx.y * 32;
    for (int i = threadIdx.y; i < 32; i += 8)
        t[i][threadIdx.x] = in[(long)(k0 + i) * N + n0 + threadIdx.x];
    __syncthreads();
    for (int i = threadIdx.y; i < 32; i += 8) {
        float v = t[threadIdx.x][i];
        oh[(long)(n0 + i) * K + k0 + threadIdx.x] = __float2half(v);
    }
}

// ---------------- fused y kernel: one CTA per token n (256 threads) ----------------
// Single DRAM pass over y: phase 1 streams y[n] -> stats/logits + fp16 smem cache;
// phase 2 softmax in smem; phase 3 weighted sum reads the smem cache.
#define FY_U     0
#define FY_YC    (FY_U + 12288)                 // 36*768 fp16 = 55296
#define FY_YD    (FY_YC + 55296)                // 36*4 float
#define FY_MU    (FY_YD + 576)
#define FY_RS    (FY_MU + 144)
#define FY_WS    (FY_RS + 144)                  // [4][36] float
#define FY_CS    (FY_WS + 576)
#define SMEM_FY  (FY_CS + 16)                   // 69040 B

__global__ __launch_bounds__(256) void fused_y(const float* __restrict__ y,
                                               const float* __restrict__ gamma,
                                               const float* __restrict__ beta) {
    extern __shared__ char sm[];
    float4* u_s  = (float4*)(sm + FY_U);
    __half* yc   = (__half*)(sm + FY_YC);
    float*  yd_s = (float*)(sm + FY_YD);
    float*  mu_s = (float*)(sm + FY_MU);
    float*  rs_s = (float*)(sm + FY_RS);
    float*  w_s  = (float*)(sm + FY_WS);
    float*  csub = (float*)(sm + FY_CS);

    const int n = blockIdx.x;
    const int tid = threadIdx.x;
    const int w = tid >> 5, lane = tid & 31;

    const float4* u4 = (const float4*)g_u;
    for (int i = tid; i < H_NUM * E4; i += 256) u_s[i] = u4[i];
    __syncthreads();

    const float4* yb = (const float4*)y + (long)n * K_NB * E4;

    // ---- phase 1: 8 warps stream rows k = w, w+8, ...; cache fp16 copy ----
    for (int k = w; k < K_NB; k += 8) {
        const float4* yr = yb + (long)k * E4;
        float4 v[6];
        float s = 0.f, sq = 0.f;
        #pragma unroll
        for (int j = 0; j < 6; j++) {
            v[j] = yr[lane + 32 * j];
            s  += v[j].x + v[j].y + v[j].z + v[j].w;
            sq += v[j].x * v[j].x + v[j].y * v[j].y + v[j].z * v[j].z + v[j].w * v[j].w;
        }
        // store fp16 copy to smem cache (cols (lane+32j)*4)
        #pragma unroll
        for (int j = 0; j < 6; j++) {
            __half2* p = (__half2*)(yc + (long)k * E_DIM + (lane + 32 * j) * 4);
            p[0] = __floats2half2_rn(v[j].x, v[j].y);
            p[1] = __floats2half2_rn(v[j].z, v[j].w);
        }
        #pragma unroll
        for (int o = 16; o; o >>= 1) {
            s  += __shfl_xor_sync(0xffffffffu, s, o);
            sq += __shfl_xor_sync(0xffffffffu, sq, o);
        }
        const float inv = 1.0f / 768.0f;
        float mean = s * inv;
        float var  = sq * inv - mean * mean;
        float rstd = rsqrtf(var + 1e-5f);

        float p0 = 0.f, p1 = 0.f, p2 = 0.f, p3 = 0.f;
        #pragma unroll
        for (int j = 0; j < 6; j++) {
            int idx = lane + 32 * j;
            float tx = v[j].x - mean, ty = v[j].y - mean, tz = v[j].z - mean, tw = v[j].w - mean;
            float4 u0 = u_s[idx];
            float4 u1 = u_s[E4 + idx];
            float4 u2 = u_s[2 * E4 + idx];
            float4 u3 = u_s[3 * E4 + idx];
            p0 += tx * u0.x + ty * u0.y + tz * u0.z + tw * u0.w;
            p1 += tx * u1.x + ty * u1.y + tz * u1.z + tw * u1.w;
            p2 += tx * u2.x + ty * u2.y + tz * u2.z + tw * u2.w;
            p3 += tx * u3.x + ty * u3.y + tz * u3.z + tw * u3.w;
        }
        #pragma unroll
        for (int o = 16; o; o >>= 1) {
            p0 += __shfl_xor_sync(0xffffffffu, p0, o);
            p1 += __shfl_xor_sync(0xffffffffu, p1, o);
            p2 += __shfl_xor_sync(0xffffffffu, p2, o);
            p3 += __shfl_xor_sync(0xffffffffu, p3, o);
        }
        if (lane == 0) {
            mu_s[k] = mean;
            rs_s[k] = rstd;
            yd_s[k * 4 + 0] = p0 * rstd;
            yd_s[k * 4 + 1] = p1 * rstd;
            yd_s[k * 4 + 2] = p2 * rstd;
            yd_s[k * 4 + 3] = p3 * rstd;
        }
    }
    __syncthreads();

    // ---- phase 2: softmax per head (warps 0..3) ----
    if (w < H_NUM) {
        int h = w;
        float l1 = (lane < K_NB) ? yd_s[lane * 4 + h] : -1e30f;
        float l2 = (lane < K_NB - 32) ? yd_s[(lane + 32) * 4 + h] : -1e30f;
        float m = fmaxf(l1, l2);
        #pragma unroll
        for (int o = 16; o; o >>= 1) m = fmaxf(m, __shfl_xor_sync(0xffffffffu, m, o));
        float e1 = (lane < K_NB) ? expf(l1 - m) : 0.f;
        float e2 = (lane < K_NB - 32) ? expf(l2 - m) : 0.f;
        float se = e1 + e2;
        #pragma unroll
        for (int o = 16; o; o >>= 1) se += __shfl_xor_sync(0xffffffffu, se, o);
        float invs = 1.0f / se;
        float wv1 = 0.f, wv2 = 0.f;
        if (lane < K_NB)      { wv1 = e1 * invs * rs_s[lane];      w_s[h * K_NB + lane]      = wv1; }
        if (lane < K_NB - 32) { wv2 = e2 * invs * rs_s[lane + 32]; w_s[h * K_NB + lane + 32] = wv2; }
        float cp = (lane < K_NB ? wv1 * mu_s[lane] : 0.f) +
                   (lane < K_NB - 32 ? wv2 * mu_s[lane + 32] : 0.f);
        #pragma unroll
        for (int o = 16; o; o >>= 1) cp += __shfl_xor_sync(0xffffffffu, cp, o);
        if (lane == 0) csub[h] = cp;
    }
    __syncthreads();

    // ---- phase 3: weighted sum from smem cache (threads 0..191, 4 cols each) ----
    if (tid < E4) {
        float acc[H_NUM][4];
        #pragma unroll
        for (int h = 0; h < H_NUM; h++)
            #pragma unroll
            for (int q = 0; q < 4; q++) acc[h][q] = 0.f;
        #pragma unroll 4
        for (int k = 0; k < K_NB; k++) {
            const __half2* p = (const __half2*)(yc + (long)k * E_DIM + tid * 4);
            float2 v01 = __half22float2(p[0]);
            float2 v23 = __half22float2(p[1]);
            #pragma unroll
            for (int h = 0; h < H_NUM; h++) {
                float wv = w_s[h * K_NB + k];
                acc[h][0] += wv * v01.x; acc[h][1] += wv * v01.y;
                acc[h][2] += wv * v23.x; acc[h][3] += wv * v23.y;
            }
        }
        #pragma unroll
        for (int h = 0; h < H_NUM; h++) {
            float4 ga = ((const float4*)gamma)[h * E4 + tid];
            float4 be = ((const float4*)beta)[h * E4 + tid];
            float c = csub[h];
            float o0 = (acc[h][0] - c) * ga.x + be.x;
            float o1 = (acc[h][1] - c) * ga.y + be.y;
            float o2 = (acc[h][2] - c) * ga.z + be.z;
            float o3 = (acc[h][3] - c) * ga.w + be.w;
            long base = ((long)h * BS_TOT + n) * E_DIM + tid * 4;
            __half2* pa = (__half2*)(g_a + base);
            pa[0] = __floats2half2_rn(o0, o1);
            pa[1] = __floats2half2_rn(o2, o3);
        }
    }
}

// ================= HMMA (mma.sync fp16) GEMM, TN=64, 3-stage pipeline =================
// D[m][n] = sum_k A[m][k]*B[n][k]
// MODE 0: cat[m][coloff+n] = half(GELU(x[m][n] + D + bias[n]))
// MODE 1: outF[m][n] = x[m][n] + GELU(D + bias[n])
#define TM 128
#define TNV 64
#define KC 32
#define ROWB   80                     // 32 halfs (64B) + 16B pad: conflict-free LDSM
#define BUF_A  (128 * ROWB)           // 10240 B
#define BUF_B  (TNV * ROWB)           // 5120 B
#define S_A    0
#define S_B    (BUF_A)
#define STAGE  (BUF_A + BUF_B)        // 15360 B
#define NSTG   3
#define GEMM_SMEM (NSTG * STAGE)      // 46080 B

template <int MODE>
__global__ __launch_bounds__(256) void gemm_mma(
    const __half* __restrict__ A, long aBatch, int lda,
    const __half* __restrict__ B, long bBatch, int ldb,
    const float* __restrict__ bias, int biasBatch,
    const float* __restrict__ x,
    float* __restrict__ outF, __half* __restrict__ outC,
    int ldc, int colBatch, int K) {
    extern __shared__ char smem[];
    uint32_t sb = smem_u32(smem);
    const int tid = threadIdx.x, w = tid >> 5, l = tid & 31;

    int z = blockIdx.z;
    A += (long)z * aBatch;
    B += (long)z * bBatch;
    bias += (long)z * biasBatch;
    const int coloff = z * colBatch;
    const int m0 = blockIdx.y * TM, n0 = blockIdx.x * TNV;
    const int wm = (w >> 2) * 64, wn = (w & 3) * 16;

    // gmem->smem: A rows (tid>>2), (tid>>2)+64; B rows (tid>>2); 16B chunk (tid&3)
    const int gr = tid >> 2, gc = tid & 3;
    const long aoff0 = ((long)(m0 + gr) * lda + gc * 8) * 2;
    const long aoff1 = aoff0 + (long)64 * lda * 2;
    const long boff0 = ((long)(n0 + gr) * ldb + gc * 8) * 2;
    const uint32_t soff0 = gr * ROWB + gc * 16;
    const uint32_t soff1 = (gr + 64) * ROWB + gc * 16;
    const char* aB = (const char*)A;
    const char* bB = (const char*)B;

    const uint32_t a_r = (l & 15) * ROWB + (l >> 4) * 16;
    const uint32_t b_r = (((l >> 4) & 1) * 8 + (l & 7)) * ROWB + ((l >> 3) & 1) * 16;

    float acc[4][2][4];
    #pragma unroll
    for (int i = 0; i < 4; i++)
        #pragma unroll
        for (int j = 0; j < 2; j++)
            #pragma unroll
            for (int q = 0; q < 4; q++) acc[i][j][q] = 0.f;

    const int NC = K / KC;

    // prologue: issue chunks 0, 1
    #pragma unroll
    for (int pc = 0; pc < 2; pc++) {
        uint32_t st = sb + pc * STAGE;
        long kb = (long)pc * KC * 2;
        CP_ASYNC16(st + S_A + soff0, aB + aoff0 + kb);
        CP_ASYNC16(st + S_A + soff1, aB + aoff1 + kb);
        CP_ASYNC16(st + S_B + soff0, bB + boff0 + kb);
        CP_COMMIT();
    }

    for (int c = 0; c < NC; c++) {
        if (c + 2 < NC) {
            uint32_t sn = sb + ((c + 2) % NSTG) * STAGE;
            long kb = (long)(c + 2) * KC * 2;
            CP_ASYNC16(sn + S_A + soff0, aB + aoff0 + kb);
            CP_ASYNC16(sn + S_A + soff1, aB + aoff1 + kb);
            CP_ASYNC16(sn + S_B + soff0, bB + boff0 + kb);
            CP_COMMIT();
            CP_WAIT(2);
        } else {
            CP_WAIT(0);
        }
        __syncthreads();

        uint32_t st = sb + (c % NSTG) * STAGE;
        #pragma unroll
        for (int kk = 0; kk < 2; kk++) {
            uint32_t kby = kk * 32;   // 16 halfs = 32B
            uint32_t ah[4][4], bh[4];
            #pragma unroll
            for (int mt = 0; mt < 4; mt++) {
                uint32_t ra = st + S_A + (wm + mt * 16) * ROWB + a_r + kby;
                LDSM_X4(ah[mt][0], ah[mt][1], ah[mt][2], ah[mt][3], ra);
            }
            {
                uint32_t rb = st + S_B + wn * ROWB + b_r + kby;
                LDSM_X4(bh[0], bh[1], bh[2], bh[3], rb);
            }
            #pragma unroll
            for (int mt = 0; mt < 4; mt++) {
                #pragma unroll
                for (int nt = 0; nt < 2; nt++) {
                    MMA16816(acc[mt][nt], ah[mt], bh[nt * 2], bh[nt * 2 + 1]);
                }
            }
        }
        __syncthreads();
    }

    // epilogue
    #pragma unroll
    for (int mt = 0; mt < 4; mt++) {
        #pragma unroll
        for (int nt = 0; nt < 2; nt++) {
            int row0 = m0 + wm + mt * 16 + (l >> 2);
            int col = n0 + wn + nt * 8 + ((l & 3) << 1);
            #pragma unroll
            for (int rh = 0; rh < 2; rh++) {
                int row = row0 + rh * 8;
                float d0 = acc[mt][nt][rh * 2 + 0];
                float d1 = acc[mt][nt][rh * 2 + 1];
                float2 xv = *(const float2*)(x + (long)row * E_DIM + col);
                float2 bv = *(const float2*)(bias + col);
                if (MODE == 0) {
                    float o0 = gelu_tanh(xv.x + d0 + bv.x);
                    float o1 = gelu_tanh(xv.y + d1 + bv.y);
                    *(__half2*)(outC + (long)row * ldc + coloff + col) =
                        __floats2half2_rn(o0, o1);
                } else {
                    float2 o;
                    o.x = xv.x + gelu_tanh(d0 + bv.x);
                    o.y = xv.y + gelu_tanh(d1 + bv.y);
                    *(float2*)(outF + (long)row * ldc + col) = o;
                }
            }
        }
    }
}

// ---------------- launch ----------------
extern "C" void kernel_launch(void* const* d_in, const int* in_sizes, int n_in,
                              void* d_out, int out_size) {
    (void)in_sizes; (void)n_in; (void)out_size;
    const float* x     = (const float*)d_in[0];   // [2048,768]
    const float* y     = (const float*)d_in[1];   // [2048,36,768]
    const float* gamma = (const float*)d_in[2];   // [4,768]
    const float* beta  = (const float*)d_in[3];   // [4,768]
    const float* W1    = (const float*)d_in[4];   // [4,768,768]
    const float* b1    = (const float*)d_in[5];   // [4,768]
    // d_in[6] = W2x, d_in[8] = b2: cancel in the softmax — unused.
    const float* W2y   = (const float*)d_in[7];   // [4,768]
    const float* Wm    = (const float*)d_in[9];   // [3072,768]
    const float* bm    = (const float*)d_in[10];  // [768]
    float* out = (float*)d_out;

    __half *p_a, *p_w1t, *p_cat, *p_wmt;
    cudaGetSymbolAddress((void**)&p_a, g_a);
    cudaGetSymbolAddress((void**)&p_w1t, g_w1t);
    cudaGetSymbolAddress((void**)&p_cat, g_cat);
    cudaGetSymbolAddress((void**)&p_wmt, g_wmt);

    cudaFuncSetAttribute(fused_y, cudaFuncAttributeMaxDynamicSharedMemorySize, SMEM_FY);
    cudaFuncSetAttribute(gemm_mma<0>, cudaFuncAttributeMaxDynamicSharedMemorySize, GEMM_SMEM);
    cudaFuncSetAttribute(gemm_mma<1>, cudaFuncAttributeMaxDynamicSharedMemorySize, GEMM_SMEM);

    prep_u<<<384, 256>>>(W1, W2y, gamma);
    transpose_h<<<dim3(24, 24, 4), dim3(32, 8)>>>(W1, 768, 768, 768L * 768,
                                                  p_w1t, 768L * 768);
    transpose_h<<<dim3(96, 24, 1), dim3(32, 8)>>>(Wm, 3072, 768, 0, p_wmt, 0);
    fused_y<<<BS_TOT, 256, SMEM_FY>>>(y, gamma, beta);

    // GEMM1 (per head): cat[:, h*768+n] = GELU(x + A_h @ W1[h]^T + b1[h])
    gemm_mma<0><<<dim3(E_DIM / TNV, BS_TOT / TM, H_NUM), 256, GEMM_SMEM>>>(
        p_a, (long)BS_TOT * E_DIM, E_DIM,
        p_w1t, (long)E_DIM * E_DIM, E_DIM,
        b1, E_DIM, x,
        nullptr, p_cat, CATD, E_DIM, E_DIM);
    // GEMM2: out = x + GELU(cat @ WmT^T + bm)
    gemm_mma<1><<<dim3(E_DIM / TNV, BS_TOT / TM, 1), 256, GEMM_SMEM>>>(
        p_cat, 0, CATD,
        p_wmt, 0, CATD,
        bm, 0, x,
        out, nullptr, E_DIM, 0, CATD);
}

// round 7
// speedup vs baseline: 3.6096x; 1.1247x over previous
#include <cuda_runtime.h>
#include <cuda_fp16.h>
#include <cstdint>

// Problem constants (fixed by setup_inputs)
#define BS_TOT 2048      // B*S
#define E_DIM  768
#define E4     192       // E/4
#define K_NB   36
#define H_NUM  4
#define CATD   (H_NUM * E_DIM)   // 3072

// ---------------- scratch (device globals; no allocations) ----------------
__device__ float g_u[H_NUM * E_DIM];                    // gamma ⊙ (W1 @ W2y)

// fp16 buffers for HMMA GEMMs
__device__ __half g_a[(long)H_NUM * BS_TOT * E_DIM];     // attention out per head
__device__ __half g_w1t[(long)H_NUM * E_DIM * E_DIM];    // W1^T per head
__device__ __half g_cat[(long)BS_TOT * CATD];            // concat head outputs
__device__ __half g_wmt[(long)E_DIM * CATD];             // Wm^T

__device__ __forceinline__ float gelu_tanh(float v) {
    const float c = 0.7978845608028654f;   // sqrt(2/pi)
    float t = tanhf(c * (v + 0.044715f * v * v * v));
    return 0.5f * v * (1.0f + t);
}

__device__ __forceinline__ uint32_t smem_u32(const void* p) {
    uint32_t a;
    asm("{ .reg .u64 t; cvta.to.shared.u64 t, %1; cvt.u32.u64 %0, t; }" : "=r"(a) : "l"(p));
    return a;
}

#define CP_ASYNC16(sm, gm) \
    asm volatile("cp.async.cg.shared.global [%0], [%1], 16;" :: "r"(sm), "l"(gm))
#define CP_COMMIT() asm volatile("cp.async.commit_group;" ::: "memory")
#define CP_WAIT(n)  asm volatile("cp.async.wait_group %0;" :: "n"(n) : "memory")

#define LDSM_X4(r0, r1, r2, r3, a) \
    asm volatile("ldmatrix.sync.aligned.m8n8.x4.shared.b16 {%0,%1,%2,%3}, [%4];" \
                 : "=r"(r0), "=r"(r1), "=r"(r2), "=r"(r3) : "r"(a))

#define MMA16816(d, a, b0v, b1v) \
    asm volatile("mma.sync.aligned.m16n8k16.row.col.f32.f16.f16.f32 " \
                 "{%0,%1,%2,%3}, {%4,%5,%6,%7}, {%8,%9}, {%0,%1,%2,%3};" \
                 : "+f"((d)[0]), "+f"((d)[1]), "+f"((d)[2]), "+f"((d)[3]) \
                 : "r"((a)[0]), "r"((a)[1]), "r"((a)[2]), "r"((a)[3]), \
                   "r"(b0v), "r"(b1v))

// ---------------- combined prep: transposes (W1, Wm) + prep_u in one launch ----
// blocks [0, 2304)      : transpose W1  (24 x 24 x 4)
// blocks [2304, 4608)   : transpose Wm  (96 x 24)
// blocks [4608, 4992)   : prep_u        (384 blocks x 8 warps)
__global__ __launch_bounds__(256) void prep_all(const float* __restrict__ W1,
                                                const float* __restrict__ Wm,
                                                const float* __restrict__ W2y,
                                                const float* __restrict__ gamma,
                                                __half* __restrict__ w1t,
                                                __half* __restrict__ wmt) {
    int b = blockIdx.x;
    if (b < 4608) {
        // transpose in[k][n] -> out[n][k] (fp16)
        const float* in;
        __half* oh;
        int K, N, k0, n0;
        if (b < 2304) {
            int z = b / 576, r = b % 576;
            in = W1 + (long)z * E_DIM * E_DIM;
            oh = w1t + (long)z * E_DIM * E_DIM;
            K = 768; N = 768;
            k0 = (r % 24) * 32; n0 = (r / 24) * 32;
        } else {
            int r = b - 2304;
            in = Wm; oh = wmt;
            K = 3072; N = 768;
            k0 = (r % 96) * 32; n0 = (r / 96) * 32;
        }
        __shared__ float t[32][33];
        int tx = threadIdx.x & 31, ty = threadIdx.x >> 5;
        for (int i = ty; i < 32; i += 8)
            t[i][tx] = in[(long)(k0 + i) * N + n0 + tx];
        __syncthreads();
        for (int i = ty; i < 32; i += 8)
            oh[(long)(n0 + i) * K + k0 + tx] = __float2half(t[tx][i]);
    } else {
        int warp = (b - 4608) * 8 + (threadIdx.x >> 5);
        int lane = threadIdx.x & 31;
        if (warp >= H_NUM * E_DIM) return;
        int h = warp / E_DIM;
        const float* wrow = W1 + (long)warp * E_DIM;
        const float* w2 = W2y + h * E_DIM;
        float s = 0.f;
        #pragma unroll 4
        for (int j = lane; j < E_DIM; j += 32) s += wrow[j] * w2[j];
        #pragma unroll
        for (int o = 16; o; o >>= 1) s += __shfl_xor_sync(0xffffffffu, s, o);
        if (lane == 0) g_u[warp] = gamma[warp] * s;
    }
}

// ---------------- fused y kernel: one CTA per token n (256 threads) ----------------
// Single DRAM pass over y with software-pipelined phase 1.
#define FY_U     0
#define FY_YC    (FY_U + 12288)                 // 36*768 fp16 = 55296
#define FY_YD    (FY_YC + 55296)                // 36*4 float
#define FY_MU    (FY_YD + 576)
#define FY_RS    (FY_MU + 144)
#define FY_WS    (FY_RS + 144)                  // [4][36] float
#define FY_CS    (FY_WS + 576)
#define SMEM_FY  (FY_CS + 16)                   // 69040 B

__global__ __launch_bounds__(256, 3) void fused_y(const float* __restrict__ y,
                                                  const float* __restrict__ gamma,
                                                  const float* __restrict__ beta) {
    extern __shared__ char sm[];
    float4* u_s  = (float4*)(sm + FY_U);
    __half* yc   = (__half*)(sm + FY_YC);
    float*  yd_s = (float*)(sm + FY_YD);
    float*  mu_s = (float*)(sm + FY_MU);
    float*  rs_s = (float*)(sm + FY_RS);
    float*  w_s  = (float*)(sm + FY_WS);
    float*  csub = (float*)(sm + FY_CS);

    const int n = blockIdx.x;
    const int tid = threadIdx.x;
    const int w = tid >> 5, lane = tid & 31;

    const float4* u4 = (const float4*)g_u;
    for (int i = tid; i < H_NUM * E4; i += 256) u_s[i] = u4[i];
    __syncthreads();

    const float4* yb = (const float4*)y + (long)n * K_NB * E4;

    // ---- phase 1: 8 warps, rows w, w+8, ... with next-row prefetch ----
    float4 v[6];
    {
        const float4* yr = yb + (long)w * E4;
        #pragma unroll
        for (int j = 0; j < 6; j++) v[j] = yr[lane + 32 * j];
    }
    for (int k = w; k < K_NB; k += 8) {
        float4 vn[6];
        const int kn = k + 8;
        if (kn < K_NB) {
            const float4* yr2 = yb + (long)kn * E4;
            #pragma unroll
            for (int j = 0; j < 6; j++) vn[j] = yr2[lane + 32 * j];
        }

        float s = 0.f, sq = 0.f;
        #pragma unroll
        for (int j = 0; j < 6; j++) {
            s  += v[j].x + v[j].y + v[j].z + v[j].w;
            sq += v[j].x * v[j].x + v[j].y * v[j].y + v[j].z * v[j].z + v[j].w * v[j].w;
        }
        // fp16 cache
        #pragma unroll
        for (int j = 0; j < 6; j++) {
            __half2* p = (__half2*)(yc + (long)k * E_DIM + (lane + 32 * j) * 4);
            p[0] = __floats2half2_rn(v[j].x, v[j].y);
            p[1] = __floats2half2_rn(v[j].z, v[j].w);
        }
        #pragma unroll
        for (int o = 16; o; o >>= 1) {
            s  += __shfl_xor_sync(0xffffffffu, s, o);
            sq += __shfl_xor_sync(0xffffffffu, sq, o);
        }
        const float inv = 1.0f / 768.0f;
        float mean = s * inv;
        float var  = sq * inv - mean * mean;
        float rstd = rsqrtf(var + 1e-5f);

        float p0 = 0.f, p1 = 0.f, p2 = 0.f, p3 = 0.f;
        #pragma unroll
        for (int j = 0; j < 6; j++) {
            int idx = lane + 32 * j;
            float tx = v[j].x - mean, ty = v[j].y - mean, tz = v[j].z - mean, tw = v[j].w - mean;
            float4 u0 = u_s[idx];
            float4 u1 = u_s[E4 + idx];
            float4 u2 = u_s[2 * E4 + idx];
            float4 u3 = u_s[3 * E4 + idx];
            p0 += tx * u0.x + ty * u0.y + tz * u0.z + tw * u0.w;
            p1 += tx * u1.x + ty * u1.y + tz * u1.z + tw * u1.w;
            p2 += tx * u2.x + ty * u2.y + tz * u2.z + tw * u2.w;
            p3 += tx * u3.x + ty * u3.y + tz * u3.z + tw * u3.w;
        }
        #pragma unroll
        for (int o = 16; o; o >>= 1) {
            p0 += __shfl_xor_sync(0xffffffffu, p0, o);
            p1 += __shfl_xor_sync(0xffffffffu, p1, o);
            p2 += __shfl_xor_sync(0xffffffffu, p2, o);
            p3 += __shfl_xor_sync(0xffffffffu, p3, o);
        }
        if (lane == 0) {
            mu_s[k] = mean;
            rs_s[k] = rstd;
            yd_s[k * 4 + 0] = p0 * rstd;
            yd_s[k * 4 + 1] = p1 * rstd;
            yd_s[k * 4 + 2] = p2 * rstd;
            yd_s[k * 4 + 3] = p3 * rstd;
        }
        #pragma unroll
        for (int j = 0; j < 6; j++) v[j] = vn[j];
    }
    __syncthreads();

    // ---- phase 2: softmax per head (warps 0..3) ----
    if (w < H_NUM) {
        int h = w;
        float l1 = (lane < K_NB) ? yd_s[lane * 4 + h] : -1e30f;
        float l2 = (lane < K_NB - 32) ? yd_s[(lane + 32) * 4 + h] : -1e30f;
        float m = fmaxf(l1, l2);
        #pragma unroll
        for (int o = 16; o; o >>= 1) m = fmaxf(m, __shfl_xor_sync(0xffffffffu, m, o));
        float e1 = (lane < K_NB) ? expf(l1 - m) : 0.f;
        float e2 = (lane < K_NB - 32) ? expf(l2 - m) : 0.f;
        float se = e1 + e2;
        #pragma unroll
        for (int o = 16; o; o >>= 1) se += __shfl_xor_sync(0xffffffffu, se, o);
        float invs = 1.0f / se;
        float wv1 = 0.f, wv2 = 0.f;
        if (lane < K_NB)      { wv1 = e1 * invs * rs_s[lane];      w_s[h * K_NB + lane]      = wv1; }
        if (lane < K_NB - 32) { wv2 = e2 * invs * rs_s[lane + 32]; w_s[h * K_NB + lane + 32] = wv2; }
        float cp = (lane < K_NB ? wv1 * mu_s[lane] : 0.f) +
                   (lane < K_NB - 32 ? wv2 * mu_s[lane + 32] : 0.f);
        #pragma unroll
        for (int o = 16; o; o >>= 1) cp += __shfl_xor_sync(0xffffffffu, cp, o);
        if (lane == 0) csub[h] = cp;
    }
    __syncthreads();

    // ---- phase 3: weighted sum from smem cache (threads 0..191, 4 cols each) ----
    if (tid < E4) {
        float acc[H_NUM][4];
        #pragma unroll
        for (int h = 0; h < H_NUM; h++)
            #pragma unroll
            for (int q = 0; q < 4; q++) acc[h][q] = 0.f;
        #pragma unroll 4
        for (int k = 0; k < K_NB; k++) {
            const __half2* p = (const __half2*)(yc + (long)k * E_DIM + tid * 4);
            float2 v01 = __half22float2(p[0]);
            float2 v23 = __half22float2(p[1]);
            #pragma unroll
            for (int h = 0; h < H_NUM; h++) {
                float wv = w_s[h * K_NB + k];
                acc[h][0] += wv * v01.x; acc[h][1] += wv * v01.y;
                acc[h][2] += wv * v23.x; acc[h][3] += wv * v23.y;
            }
        }
        #pragma unroll
        for (int h = 0; h < H_NUM; h++) {
            float4 ga = ((const float4*)gamma)[h * E4 + tid];
            float4 be = ((const float4*)beta)[h * E4 + tid];
            float c = csub[h];
            float o0 = (acc[h][0] - c) * ga.x + be.x;
            float o1 = (acc[h][1] - c) * ga.y + be.y;
            float o2 = (acc[h][2] - c) * ga.z + be.z;
            float o3 = (acc[h][3] - c) * ga.w + be.w;
            long base = ((long)h * BS_TOT + n) * E_DIM + tid * 4;
            __half2* pa = (__half2*)(g_a + base);
            pa[0] = __floats2half2_rn(o0, o1);
            pa[1] = __floats2half2_rn(o2, o3);
        }
    }
}

// ================= HMMA (mma.sync fp16) GEMM, TN=64, 4-stage, 1 barrier/iter =====
// D[m][n] = sum_k A[m][k]*B[n][k]
// MODE 0: cat[m][coloff+n] = half(GELU(x[m][n] + D + bias[n]))
// MODE 1: outF[m][n] = x[m][n] + GELU(D + bias[n])
#define TNV 64
#define KC 32
#define ROWB   80                     // 32 halfs (64B) + 16B pad: conflict-free LDSM
#define NSTG   4

template <int MODE, int TMv>
__global__ __launch_bounds__(256) void gemm_mma(
    const __half* __restrict__ A, long aBatch, int lda,
    const __half* __restrict__ B, long bBatch, int ldb,
    const float* __restrict__ bias, int biasBatch,
    const float* __restrict__ x,
    float* __restrict__ outF, __half* __restrict__ outC,
    int ldc, int colBatch, int K) {
    constexpr int BUF_A = TMv * ROWB;
    constexpr int BUF_B = TNV * ROWB;
    constexpr int STAGE = BUF_A + BUF_B;
    constexpr int MT = TMv / 32;          // m-tiles (16 rows) per warp
    constexpr int AL = TMv / 64;          // A rows loaded per thread

    extern __shared__ char smem[];
    uint32_t sb = smem_u32(smem);
    const int tid = threadIdx.x, w = tid >> 5, l = tid & 31;

    int z = blockIdx.z;
    A += (long)z * aBatch;
    B += (long)z * bBatch;
    bias += (long)z * biasBatch;
    const int coloff = z * colBatch;
    const int m0 = blockIdx.y * TMv, n0 = blockIdx.x * TNV;
    const int wm = (w >> 2) * (TMv / 2), wn = (w & 3) * 16;

    const int gr = tid >> 2, gc = tid & 3;
    const long aoff0 = ((long)(m0 + gr) * lda + gc * 8) * 2;
    const long aoff1 = aoff0 + (long)64 * lda * 2;
    const long boff0 = ((long)(n0 + gr) * ldb + gc * 8) * 2;
    const uint32_t soff0 = gr * ROWB + gc * 16;
    const uint32_t soff1 = (gr + 64) * ROWB + gc * 16;
    const char* aB = (const char*)A;
    const char* bB = (const char*)B;

    const uint32_t a_r = (l & 15) * ROWB + (l >> 4) * 16;
    const uint32_t b_r = (((l >> 4) & 1) * 8 + (l & 7)) * ROWB + ((l >> 3) & 1) * 16;

    float acc[MT][2][4];
    #pragma unroll
    for (int i = 0; i < MT; i++)
        #pragma unroll
        for (int j = 0; j < 2; j++)
            #pragma unroll
            for (int q = 0; q < 4; q++) acc[i][j][q] = 0.f;

    const int NC = K / KC;

    // prologue: chunks 0..2
    #pragma unroll
    for (int pc = 0; pc < 3; pc++) {
        uint32_t st = sb + pc * STAGE;
        long kb = (long)pc * KC * 2;
        CP_ASYNC16(st + soff0, aB + aoff0 + kb);
        if (AL > 1) CP_ASYNC16(st + soff1, aB + aoff1 + kb);
        CP_ASYNC16(st + BUF_A + soff0, bB + boff0 + kb);
        CP_COMMIT();
    }

    for (int c = 0; c < NC; c++) {
        CP_WAIT(2);
        __syncthreads();

        uint32_t st = sb + (c % NSTG) * STAGE;
        #pragma unroll
        for (int kk = 0; kk < 2; kk++) {
            uint32_t kby = kk * 32;   // 16 halfs = 32B
            uint32_t ah[MT][4], bh[4];
            #pragma unroll
            for (int mt = 0; mt < MT; mt++) {
                uint32_t ra = st + (wm + mt * 16) * ROWB + a_r + kby;
                LDSM_X4(ah[mt][0], ah[mt][1], ah[mt][2], ah[mt][3], ra);
            }
            {
                uint32_t rb = st + BUF_A + wn * ROWB + b_r + kby;
                LDSM_X4(bh[0], bh[1], bh[2], bh[3], rb);
            }
            #pragma unroll
            for (int mt = 0; mt < MT; mt++) {
                #pragma unroll
                for (int nt = 0; nt < 2; nt++) {
                    MMA16816(acc[mt][nt], ah[mt], bh[nt * 2], bh[nt * 2 + 1]);
                }
            }
        }

        // prefetch chunk c+3 into stage (c+3)%4 == (c-1)%4 (free after this iter's barrier)
        if (c + 3 < NC) {
            uint32_t sn = sb + ((c + 3) % NSTG) * STAGE;
            long kb = (long)(c + 3) * KC * 2;
            CP_ASYNC16(sn + soff0, aB + aoff0 + kb);
            if (AL > 1) CP_ASYNC16(sn + soff1, aB + aoff1 + kb);
            CP_ASYNC16(sn + BUF_A + soff0, bB + boff0 + kb);
            CP_COMMIT();
        }
    }

    // epilogue
    #pragma unroll
    for (int mt = 0; mt < MT; mt++) {
        #pragma unroll
        for (int nt = 0; nt < 2; nt++) {
            int row0 = m0 + wm + mt * 16 + (l >> 2);
            int col = n0 + wn + nt * 8 + ((l & 3) << 1);
            #pragma unroll
            for (int rh = 0; rh < 2; rh++) {
                int row = row0 + rh * 8;
                float d0 = acc[mt][nt][rh * 2 + 0];
                float d1 = acc[mt][nt][rh * 2 + 1];
                float2 xv = *(const float2*)(x + (long)row * E_DIM + col);
                float2 bv = *(const float2*)(bias + col);
                if (MODE == 0) {
                    float o0 = gelu_tanh(xv.x + d0 + bv.x);
                    float o1 = gelu_tanh(xv.y + d1 + bv.y);
                    *(__half2*)(outC + (long)row * ldc + coloff + col) =
                        __floats2half2_rn(o0, o1);
                } else {
                    float2 o;
                    o.x = xv.x + gelu_tanh(d0 + bv.x);
                    o.y = xv.y + gelu_tanh(d1 + bv.y);
                    *(float2*)(outF + (long)row * ldc + col) = o;
                }
            }
        }
    }
}

#define GEMM_SMEM_128 (NSTG * (128 * ROWB + TNV * ROWB))   // 61440
#define GEMM_SMEM_64  (NSTG * (64 * ROWB + TNV * ROWB))    // 40960

// ---------------- launch ----------------
extern "C" void kernel_launch(void* const* d_in, const int* in_sizes, int n_in,
                              void* d_out, int out_size) {
    (void)in_sizes; (void)n_in; (void)out_size;
    const float* x     = (const float*)d_in[0];   // [2048,768]
    const float* y     = (const float*)d_in[1];   // [2048,36,768]
    const float* gamma = (const float*)d_in[2];   // [4,768]
    const float* beta  = (const float*)d_in[3];   // [4,768]
    const float* W1    = (const float*)d_in[4];   // [4,768,768]
    const float* b1    = (const float*)d_in[5];   // [4,768]
    // d_in[6] = W2x, d_in[8] = b2: cancel in the softmax — unused.
    const float* W2y   = (const float*)d_in[7];   // [4,768]
    const float* Wm    = (const float*)d_in[9];   // [3072,768]
    const float* bm    = (const float*)d_in[10];  // [768]
    float* out = (float*)d_out;

    __half *p_a, *p_w1t, *p_cat, *p_wmt;
    cudaGetSymbolAddress((void**)&p_a, g_a);
    cudaGetSymbolAddress((void**)&p_w1t, g_w1t);
    cudaGetSymbolAddress((void**)&p_cat, g_cat);
    cudaGetSymbolAddress((void**)&p_wmt, g_wmt);

    cudaFuncSetAttribute(fused_y, cudaFuncAttributeMaxDynamicSharedMemorySize, SMEM_FY);
    cudaFuncSetAttribute(gemm_mma<0, 128>, cudaFuncAttributeMaxDynamicSharedMemorySize, GEMM_SMEM_128);
    cudaFuncSetAttribute(gemm_mma<1, 64>, cudaFuncAttributeMaxDynamicSharedMemorySize, GEMM_SMEM_64);

    prep_all<<<4992, 256>>>(W1, Wm, W2y, gamma, p_w1t, p_wmt);
    fused_y<<<BS_TOT, 256, SMEM_FY>>>(y, gamma, beta);

    // GEMM1 (per head): cat[:, h*768+n] = GELU(x + A_h @ W1[h]^T + b1[h])
    gemm_mma<0, 128><<<dim3(E_DIM / TNV, BS_TOT / 128, H_NUM), 256, GEMM_SMEM_128>>>(
        p_a, (long)BS_TOT * E_DIM, E_DIM,
        p_w1t, (long)E_DIM * E_DIM, E_DIM,
        b1, E_DIM, x,
        nullptr, p_cat, CATD, E_DIM, E_DIM);
    // GEMM2: out = x + GELU(cat @ WmT^T + bm)
    gemm_mma<1, 64><<<dim3(E_DIM / TNV, BS_TOT / 64, 1), 256, GEMM_SMEM_64>>>(
        p_cat, 0, CATD,
        p_wmt, 0, CATD,
        bm, 0, x,
        out, nullptr, E_DIM, 0, CATD);
}

// round 9
// speedup vs baseline: 3.8529x; 1.0674x over previous
#include <cuda_runtime.h>
#include <cuda_fp16.h>
#include <cstdint>

// Problem constants (fixed by setup_inputs)
#define BS_TOT 2048      // B*S
#define E_DIM  768
#define E4     192       // E/4
#define K_NB   36
#define H_NUM  4
#define CATD   (H_NUM * E_DIM)   // 3072

// ---------------- scratch (device globals; no allocations) ----------------
__device__ float g_u[H_NUM * E_DIM];                    // gamma ⊙ (W1 @ W2y)

// fp16 buffers for HMMA GEMMs
__device__ __half g_a[(long)H_NUM * BS_TOT * E_DIM];     // attention out per head
__device__ __half g_w1t[(long)H_NUM * E_DIM * E_DIM];    // W1^T per head
__device__ __half g_cat[(long)BS_TOT * CATD];            // concat head outputs
__device__ __half g_wmt[(long)E_DIM * CATD];             // Wm^T

__device__ __forceinline__ float gelu_tanh(float v) {
    const float c = 0.7978845608028654f;   // sqrt(2/pi)
    float t = tanhf(c * (v + 0.044715f * v * v * v));
    return 0.5f * v * (1.0f + t);
}

__device__ __forceinline__ uint32_t smem_u32(const void* p) {
    uint32_t a;
    asm("{ .reg .u64 t; cvta.to.shared.u64 t, %1; cvt.u32.u64 %0, t; }" : "=r"(a) : "l"(p));
    return a;
}

#define CP_ASYNC16(sm, gm) \
    asm volatile("cp.async.cg.shared.global [%0], [%1], 16;" :: "r"(sm), "l"(gm))
#define CP_COMMIT() asm volatile("cp.async.commit_group;" ::: "memory")
#define CP_WAIT(n)  asm volatile("cp.async.wait_group %0;" :: "n"(n) : "memory")

#define LDSM_X4(r0, r1, r2, r3, a) \
    asm volatile("ldmatrix.sync.aligned.m8n8.x4.shared.b16 {%0,%1,%2,%3}, [%4];" \
                 : "=r"(r0), "=r"(r1), "=r"(r2), "=r"(r3) : "r"(a))

#define MMA16816(d, a, b0v, b1v) \
    asm volatile("mma.sync.aligned.m16n8k16.row.col.f32.f16.f16.f32 " \
                 "{%0,%1,%2,%3}, {%4,%5,%6,%7}, {%8,%9}, {%0,%1,%2,%3};" \
                 : "+f"((d)[0]), "+f"((d)[1]), "+f"((d)[2]), "+f"((d)[3]) \
                 : "r"((a)[0]), "r"((a)[1]), "r"((a)[2]), "r"((a)[3]), \
                   "r"(b0v), "r"(b1v))

// ---------------- combined prep: transposes (W1, Wm) + prep_u in one launch ----
__global__ __launch_bounds__(256) void prep_all(const float* __restrict__ W1,
                                                const float* __restrict__ Wm,
                                                const float* __restrict__ W2y,
                                                const float* __restrict__ gamma,
                                                __half* __restrict__ w1t,
                                                __half* __restrict__ wmt) {
    int b = blockIdx.x;
    if (b < 4608) {
        const float* in;
        __half* oh;
        int K, N, k0, n0;
        if (b < 2304) {
            int z = b / 576, r = b % 576;
            in = W1 + (long)z * E_DIM * E_DIM;
            oh = w1t + (long)z * E_DIM * E_DIM;
            K = 768; N = 768;
            k0 = (r % 24) * 32; n0 = (r / 24) * 32;
        } else {
            int r = b - 2304;
            in = Wm; oh = wmt;
            K = 3072; N = 768;
            k0 = (r % 96) * 32; n0 = (r / 96) * 32;
        }
        __shared__ float t[32][33];
        int tx = threadIdx.x & 31, ty = threadIdx.x >> 5;
        for (int i = ty; i < 32; i += 8)
            t[i][tx] = in[(long)(k0 + i) * N + n0 + tx];
        __syncthreads();
        for (int i = ty; i < 32; i += 8)
            oh[(long)(n0 + i) * K + k0 + tx] = __float2half(t[tx][i]);
    } else {
        int warp = (b - 4608) * 8 + (threadIdx.x >> 5);
        int lane = threadIdx.x & 31;
        if (warp >= H_NUM * E_DIM) return;
        int h = warp / E_DIM;
        const float* wrow = W1 + (long)warp * E_DIM;
        const float* w2 = W2y + h * E_DIM;
        float s = 0.f;
        #pragma unroll 4
        for (int j = lane; j < E_DIM; j += 32) s += wrow[j] * w2[j];
        #pragma unroll
        for (int o = 16; o; o >>= 1) s += __shfl_xor_sync(0xffffffffu, s, o);
        if (lane == 0) g_u[warp] = gamma[warp] * s;
    }
}

// ---------------- fused y kernel: one CTA per token n (256 threads, occ 4) -----
// Phase 1: DRAM stream of y[n] -> stats/logits; Phase 2: smem softmax;
// Phase 3: weighted sum re-reads y[n] (L2-hot: 4*148*110KB = 65MB < 126MB L2).
__global__ __launch_bounds__(256, 4) void fused_y(const float* __restrict__ y,
                                                  const float* __restrict__ gamma,
                                                  const float* __restrict__ beta) {
    __shared__ float4 u_s[H_NUM * E4];     // 12 KB
    __shared__ float yd_s[K_NB * 4];
    __shared__ float mu_s[K_NB];
    __shared__ float rs_s[K_NB];
    __shared__ float w_s[H_NUM * K_NB];
    __shared__ float csub[H_NUM];

    const int n = blockIdx.x;
    const int tid = threadIdx.x;
    const int w = tid >> 5, lane = tid & 31;

    const float4* u4 = (const float4*)g_u;
    for (int i = tid; i < H_NUM * E4; i += 256) u_s[i] = u4[i];
    __syncthreads();

    const float4* yb = (const float4*)y + (long)n * K_NB * E4;

    // ---- phase 1: 8 warps, rows w, w+8, ... with next-row prefetch ----
    float4 v[6];
    {
        const float4* yr = yb + (long)w * E4;
        #pragma unroll
        for (int j = 0; j < 6; j++) v[j] = yr[lane + 32 * j];
    }
    for (int k = w; k < K_NB; k += 8) {
        float4 vn[6];
        const int kn = k + 8;
        if (kn < K_NB) {
            const float4* yr2 = yb + (long)kn * E4;
            #pragma unroll
            for (int j = 0; j < 6; j++) vn[j] = yr2[lane + 32 * j];
        }

        float s = 0.f, sq = 0.f;
        #pragma unroll
        for (int j = 0; j < 6; j++) {
            s  += v[j].x + v[j].y + v[j].z + v[j].w;
            sq += v[j].x * v[j].x + v[j].y * v[j].y + v[j].z * v[j].z + v[j].w * v[j].w;
        }
        #pragma unroll
        for (int o = 16; o; o >>= 1) {
            s  += __shfl_xor_sync(0xffffffffu, s, o);
            sq += __shfl_xor_sync(0xffffffffu, sq, o);
        }
        const float inv = 1.0f / 768.0f;
        float mean = s * inv;
        float var  = sq * inv - mean * mean;
        float rstd = rsqrtf(var + 1e-5f);

        float p0 = 0.f, p1 = 0.f, p2 = 0.f, p3 = 0.f;
        #pragma unroll
        for (int j = 0; j < 6; j++) {
            int idx = lane + 32 * j;
            float tx = v[j].x - mean, ty = v[j].y - mean, tz = v[j].z - mean, tw = v[j].w - mean;
            float4 u0 = u_s[idx];
            float4 u1 = u_s[E4 + idx];
            float4 u2 = u_s[2 * E4 + idx];
            float4 u3 = u_s[3 * E4 + idx];
            p0 += tx * u0.x + ty * u0.y + tz * u0.z + tw * u0.w;
            p1 += tx * u1.x + ty * u1.y + tz * u1.z + tw * u1.w;
            p2 += tx * u2.x + ty * u2.y + tz * u2.z + tw * u2.w;
            p3 += tx * u3.x + ty * u3.y + tz * u3.z + tw * u3.w;
        }
        #pragma unroll
        for (int o = 16; o; o >>= 1) {
            p0 += __shfl_xor_sync(0xffffffffu, p0, o);
            p1 += __shfl_xor_sync(0xffffffffu, p1, o);
            p2 += __shfl_xor_sync(0xffffffffu, p2, o);
            p3 += __shfl_xor_sync(0xffffffffu, p3, o);
        }
        if (lane == 0) {
            mu_s[k] = mean;
            rs_s[k] = rstd;
            yd_s[k * 4 + 0] = p0 * rstd;
            yd_s[k * 4 + 1] = p1 * rstd;
            yd_s[k * 4 + 2] = p2 * rstd;
            yd_s[k * 4 + 3] = p3 * rstd;
        }
        #pragma unroll
        for (int j = 0; j < 6; j++) v[j] = vn[j];
    }
    __syncthreads();

    // ---- phase 2: softmax per head (warps 0..3) ----
    if (w < H_NUM) {
        int h = w;
        float l1 = (lane < K_NB) ? yd_s[lane * 4 + h] : -1e30f;
        float l2 = (lane < K_NB - 32) ? yd_s[(lane + 32) * 4 + h] : -1e30f;
        float m = fmaxf(l1, l2);
        #pragma unroll
        for (int o = 16; o; o >>= 1) m = fmaxf(m, __shfl_xor_sync(0xffffffffu, m, o));
        float e1 = (lane < K_NB) ? expf(l1 - m) : 0.f;
        float e2 = (lane < K_NB - 32) ? expf(l2 - m) : 0.f;
        float se = e1 + e2;
        #pragma unroll
        for (int o = 16; o; o >>= 1) se += __shfl_xor_sync(0xffffffffu, se, o);
        float invs = 1.0f / se;
        float wv1 = 0.f, wv2 = 0.f;
        if (lane < K_NB)      { wv1 = e1 * invs * rs_s[lane];      w_s[h * K_NB + lane]      = wv1; }
        if (lane < K_NB - 32) { wv2 = e2 * invs * rs_s[lane + 32]; w_s[h * K_NB + lane + 32] = wv2; }
        float cp = (lane < K_NB ? wv1 * mu_s[lane] : 0.f) +
                   (lane < K_NB - 32 ? wv2 * mu_s[lane + 32] : 0.f);
        #pragma unroll
        for (int o = 16; o; o >>= 1) cp += __shfl_xor_sync(0xffffffffu, cp, o);
        if (lane == 0) csub[h] = cp;
    }
    __syncthreads();

    // ---- phase 3: weighted sum from L2 (threads 0..191, one float4 col each) ----
    if (tid < E4) {
        float acc[H_NUM][4];
        #pragma unroll
        for (int h = 0; h < H_NUM; h++)
            #pragma unroll
            for (int q = 0; q < 4; q++) acc[h][q] = 0.f;
        #pragma unroll 4
        for (int k = 0; k < K_NB; k++) {
            float4 vv = yb[k * E4 + tid];
            #pragma unroll
            for (int h = 0; h < H_NUM; h++) {
                float wv = w_s[h * K_NB + k];
                acc[h][0] += wv * vv.x; acc[h][1] += wv * vv.y;
                acc[h][2] += wv * vv.z; acc[h][3] += wv * vv.w;
            }
        }
        #pragma unroll
        for (int h = 0; h < H_NUM; h++) {
            float4 ga = ((const float4*)gamma)[h * E4 + tid];
            float4 be = ((const float4*)beta)[h * E4 + tid];
            float c = csub[h];
            float o0 = (acc[h][0] - c) * ga.x + be.x;
            float o1 = (acc[h][1] - c) * ga.y + be.y;
            float o2 = (acc[h][2] - c) * ga.z + be.z;
            float o3 = (acc[h][3] - c) * ga.w + be.w;
            long base = ((long)h * BS_TOT + n) * E_DIM + tid * 4;
            __half2* pa = (__half2*)(g_a + base);
            pa[0] = __floats2half2_rn(o0, o1);
            pa[1] = __floats2half2_rn(o2, o3);
        }
    }
}

// ========== HMMA GEMM: TM=64, TN=64, KC=64, 3-stage, one barrier/iter ==========
// D[m][n] = sum_k A[m][k]*B[n][k]
// MODE 0: cat[m][coloff+n] = half(GELU(x[m][n] + D + bias[n]))
// MODE 1: outF[m][n] = x[m][n] + GELU(D + bias[n])
//
// cp.async group invariant: ONE commit_group per iteration, unconditionally
// (empty groups at the tail). At iteration c exactly groups g0..g_{c+1} are
// committed, so wait_group(1) provably drains chunk c's group -- including
// the final iterations. (R8's conditional commit broke this at the tail and
// raced.)
#define TMV 64
#define TNV 64
#define KC 64
#define ROWB 144                      // 64 halfs (128B) + 16B pad; stride 36 banks -> conflict-free
#define NSTG 3
#define BUF_A (TMV * ROWB)
#define BUF_B (TNV * ROWB)
#define STAGE (BUF_A + BUF_B)         // 18432 B
#define GEMM_SMEM (NSTG * STAGE)      // 55296 B

template <int MODE>
__global__ __launch_bounds__(256) void gemm_mma(
    const __half* __restrict__ A, long aBatch, int lda,
    const __half* __restrict__ B, long bBatch, int ldb,
    const float* __restrict__ bias, int biasBatch,
    const float* __restrict__ x,
    float* __restrict__ outF, __half* __restrict__ outC,
    int ldc, int colBatch, int K) {
    extern __shared__ char smem[];
    uint32_t sb = smem_u32(smem);
    const int tid = threadIdx.x, w = tid >> 5, l = tid & 31;

    int z = blockIdx.z;
    A += (long)z * aBatch;
    B += (long)z * bBatch;
    bias += (long)z * biasBatch;
    const int coloff = z * colBatch;
    const int m0 = blockIdx.y * TMV, n0 = blockIdx.x * TNV;
    const int wm = (w >> 2) * 32, wn = (w & 3) * 16;

    // gmem->smem: 32 rows per pass, 8x16B chunks per row (KC=64 halfs = 128B)
    const int gr = tid >> 3, gc = tid & 7;
    const long aoff0 = ((long)(m0 + gr) * lda + gc * 8) * 2;
    const long aoff1 = aoff0 + (long)32 * lda * 2;
    const long boff0 = ((long)(n0 + gr) * ldb + gc * 8) * 2;
    const long boff1 = boff0 + (long)32 * ldb * 2;
    const uint32_t soff0 = gr * ROWB + gc * 16;
    const uint32_t soff1 = (gr + 32) * ROWB + gc * 16;
    const char* aB = (const char*)A;
    const char* bB = (const char*)B;

    const uint32_t a_r = (l & 15) * ROWB + (l >> 4) * 16;
    const uint32_t b_r = (((l >> 4) & 1) * 8 + (l & 7)) * ROWB + ((l >> 3) & 1) * 16;

    float acc[2][2][4];
    #pragma unroll
    for (int i = 0; i < 2; i++)
        #pragma unroll
        for (int j = 0; j < 2; j++)
            #pragma unroll
            for (int q = 0; q < 4; q++) acc[i][j][q] = 0.f;

    const int NC = K / KC;

    // prologue: chunks 0, 1 (groups g0, g1)
    #pragma unroll
    for (int pc = 0; pc < 2; pc++) {
        uint32_t st = sb + pc * STAGE;
        long kb = (long)pc * KC * 2;
        CP_ASYNC16(st + soff0, aB + aoff0 + kb);
        CP_ASYNC16(st + soff1, aB + aoff1 + kb);
        CP_ASYNC16(st + BUF_A + soff0, bB + boff0 + kb);
        CP_ASYNC16(st + BUF_A + soff1, bB + boff1 + kb);
        CP_COMMIT();
    }

    for (int c = 0; c < NC; c++) {
        // groups committed so far: g0..g_{c+1}; wait_group(1) => chunk c landed
        CP_WAIT(1);
        __syncthreads();

        uint32_t st = sb + (c % NSTG) * STAGE;
        #pragma unroll
        for (int kk = 0; kk < 4; kk++) {
            uint32_t kby = kk * 32;   // 16 halfs = 32B
            uint32_t ah[2][4], bh[4];
            #pragma unroll
            for (int mt = 0; mt < 2; mt++) {
                uint32_t ra = st + (wm + mt * 16) * ROWB + a_r + kby;
                LDSM_X4(ah[mt][0], ah[mt][1], ah[mt][2], ah[mt][3], ra);
            }
            {
                uint32_t rb = st + BUF_A + wn * ROWB + b_r + kby;
                LDSM_X4(bh[0], bh[1], bh[2], bh[3], rb);
            }
            #pragma unroll
            for (int mt = 0; mt < 2; mt++) {
                #pragma unroll
                for (int nt = 0; nt < 2; nt++) {
                    MMA16816(acc[mt][nt], ah[mt], bh[nt * 2], bh[nt * 2 + 1]);
                }
            }
        }

        // prefetch chunk c+2 into stage (c+2)%3 == (c-1)%3 (free: all warps past
        // this iter's barrier). Commit UNCONDITIONALLY to keep group accounting.
        if (c + 2 < NC) {
            uint32_t sn = sb + ((c + 2) % NSTG) * STAGE;
            long kb = (long)(c + 2) * KC * 2;
            CP_ASYNC16(sn + soff0, aB + aoff0 + kb);
            CP_ASYNC16(sn + soff1, aB + aoff1 + kb);
            CP_ASYNC16(sn + BUF_A + soff0, bB + boff0 + kb);
            CP_ASYNC16(sn + BUF_A + soff1, bB + boff1 + kb);
        }
        CP_COMMIT();
    }

    // epilogue
    #pragma unroll
    for (int mt = 0; mt < 2; mt++) {
        #pragma unroll
        for (int nt = 0; nt < 2; nt++) {
            int row0 = m0 + wm + mt * 16 + (l >> 2);
            int col = n0 + wn + nt * 8 + ((l & 3) << 1);
            #pragma unroll
            for (int rh = 0; rh < 2; rh++) {
                int row = row0 + rh * 8;
                float d0 = acc[mt][nt][rh * 2 + 0];
                float d1 = acc[mt][nt][rh * 2 + 1];
                float2 xv = *(const float2*)(x + (long)row * E_DIM + col);
                float2 bv = *(const float2*)(bias + col);
                if (MODE == 0) {
                    float o0 = gelu_tanh(xv.x + d0 + bv.x);
                    float o1 = gelu_tanh(xv.y + d1 + bv.y);
                    *(__half2*)(outC + (long)row * ldc + coloff + col) =
                        __floats2half2_rn(o0, o1);
                } else {
                    float2 o;
                    o.x = xv.x + gelu_tanh(d0 + bv.x);
                    o.y = xv.y + gelu_tanh(d1 + bv.y);
                    *(float2*)(outF + (long)row * ldc + col) = o;
                }
            }
        }
    }
}

// ---------------- launch ----------------
extern "C" void kernel_launch(void* const* d_in, const int* in_sizes, int n_in,
                              void* d_out, int out_size) {
    (void)in_sizes; (void)n_in; (void)out_size;
    const float* x     = (const float*)d_in[0];   // [2048,768]
    const float* y     = (const float*)d_in[1];   // [2048,36,768]
    const float* gamma = (const float*)d_in[2];   // [4,768]
    const float* beta  = (const float*)d_in[3];   // [4,768]
    const float* W1    = (const float*)d_in[4];   // [4,768,768]
    const float* b1    = (const float*)d_in[5];   // [4,768]
    // d_in[6] = W2x, d_in[8] = b2: cancel in the softmax — unused.
    const float* W2y   = (const float*)d_in[7];   // [4,768]
    const float* Wm    = (const float*)d_in[9];   // [3072,768]
    const float* bm    = (const float*)d_in[10];  // [768]
    float* out = (float*)d_out;

    __half *p_a, *p_w1t, *p_cat, *p_wmt;
    cudaGetSymbolAddress((void**)&p_a, g_a);
    cudaGetSymbolAddress((void**)&p_w1t, g_w1t);
    cudaGetSymbolAddress((void**)&p_cat, g_cat);
    cudaGetSymbolAddress((void**)&p_wmt, g_wmt);

    cudaFuncSetAttribute(gemm_mma<0>, cudaFuncAttributeMaxDynamicSharedMemorySize, GEMM_SMEM);
    cudaFuncSetAttribute(gemm_mma<1>, cudaFuncAttributeMaxDynamicSharedMemorySize, GEMM_SMEM);

    prep_all<<<4992, 256>>>(W1, Wm, W2y, gamma, p_w1t, p_wmt);
    fused_y<<<BS_TOT, 256>>>(y, gamma, beta);

    // GEMM1 (per head): cat[:, h*768+n] = GELU(x + A_h @ W1[h]^T + b1[h])
    gemm_mma<0><<<dim3(E_DIM / TNV, BS_TOT / TMV, H_NUM), 256, GEMM_SMEM>>>(
        p_a, (long)BS_TOT * E_DIM, E_DIM,
        p_w1t, (long)E_DIM * E_DIM, E_DIM,
        b1, E_DIM, x,
        nullptr, p_cat, CATD, E_DIM, E_DIM);
    // GEMM2: out = x + GELU(cat @ WmT^T + bm)
    gemm_mma<1><<<dim3(E_DIM / TNV, BS_TOT / TMV, 1), 256, GEMM_SMEM>>>(
        p_cat, 0, CATD,
        p_wmt, 0, CATD,
        bm, 0, x,
        out, nullptr, E_DIM, 0, CATD);
}